// round 13
// baseline (speedup 1.0000x reference)
#include <cuda_runtime.h>
#include <cuda_bf16.h>
#include <float.h>
#include <math.h>

#define LL 512
#define DD 256
#define PP 20
#define NB 16
#define NBLL (NB*LL)
#define EPSF 1e-8f
#define NEGF -10000000.0f
#define MF4 (4*PP)

typedef unsigned long long u64;

__device__ __forceinline__ void ffma2(u64 &d, u64 a, u64 b) {
    asm("fma.rn.f32x2 %0, %1, %2, %0;" : "+l"(d) : "l"(a), "l"(b));
}
// warp-level bf16 tensor-core MMA (sm_80+, plain target)
__device__ __forceinline__ void mma16816(float* c, const unsigned* a, const unsigned* b) {
    asm volatile("mma.sync.aligned.m16n8k16.row.col.f32.bf16.bf16.f32 "
        "{%0,%1,%2,%3}, {%4,%5,%6,%7}, {%8,%9}, {%0,%1,%2,%3};"
        : "+f"(c[0]), "+f"(c[1]), "+f"(c[2]), "+f"(c[3])
        : "r"(a[0]), "r"(a[1]), "r"(a[2]), "r"(a[3]), "r"(b[0]), "r"(b[1]));
}

// ---------------- device scratch (allocation-free) ----------------
static __device__ float g_raw[NB*LL*LL];
static __device__ __nv_bfloat16 g_ahi[PP*NBLL*DD];   // (a*ws2_p) hi
static __device__ __nv_bfloat16 g_alo[PP*NBLL*DD];   // (a*ws2_p) lo
static __device__ __nv_bfloat16 g_a0hi[NBLL*DD];     // a hi (unweighted)
static __device__ __nv_bfloat16 g_a0lo[NBLL*DD];     // a lo
static __device__ __nv_bfloat16 g_bhi[NBLL*DD];
static __device__ __nv_bfloat16 g_blo[NBLL*DD];
static __device__ float g_s2m[NB*LL*DD];
static __device__ float g_s1m[NB*LL*DD];
static __device__ float g_nra[NBLL];
static __device__ float g_nrb[NBLL];
static __device__ float g_rowmax[NBLL];
static __device__ float g_rowsuminv[NBLL];
static __device__ float g_arowsuminv[NBLL];
static __device__ float g_amax2[NBLL];
static __device__ float g_colmax[NBLL];
static __device__ float g_colsuminv[NBLL];
static __device__ float g_acolsuminv[NBLL];
static __device__ float g_amax1[NBLL];
static __device__ float g_na2[PP*NBLL];   // [p][bl]
static __device__ float g_nb2[PP*NBLL];   // [p][bl]
static __device__ float g_ws1[PP*DD];
static __device__ float g_ws2[PP*DD];
static __device__ float g_ws3[PP*DD];
static __device__ float g_ws4[PP*DD];
static __device__ float g_nbl[NB*PP];
static __device__ float g_nal[NB*PP];
static __device__ float g_wn[PP];

__device__ __forceinline__ void atomicMaxF(float* addr, float v) {
    int old = __float_as_int(*addr);
    while (__int_as_float(old) < v) {
        int prev = atomicCAS((int*)addr, old, __float_as_int(v));
        if (prev == old) break;
        old = prev;
    }
}

// ---------------- prep: squared weights + wn + mm_b init ----------------
__global__ void k_prep(const float* w1, const float* w2, const float* w3, const float* w4,
                       float* out_mb) {
    int p = blockIdx.x, d = threadIdx.x;
    float v1 = w1[p*DD+d]; g_ws1[p*DD+d] = v1*v1;
    float v2 = w2[p*DD+d]; g_ws2[p*DD+d] = v2*v2;
    float v3 = w3[p*DD+d]; g_ws3[p*DD+d] = v3*v3;
    float v4 = w4[p*DD+d]; float s4 = v4*v4; g_ws4[p*DD+d] = s4;
    __shared__ float red[256];
    red[d] = s4; __syncthreads();
    for (int o = 128; o; o >>= 1) { if (d < o) red[d] += red[d+o]; __syncthreads(); }
    if (d == 0) g_wn[p] = sqrtf(red[0]);
    for (int idx = blockIdx.x*256 + d; idx < NB*LL*PP; idx += PP*256) {
        int bl = idx / PP, pp = idx % PP;
        out_mb[bl*MF4 + PP + pp] = -FLT_MAX;
    }
}

// ---------------- split a, b into bf16 hi/lo (unweighted) ----------------
__global__ void k_absplit(const float* A, const float* Bm) {
    int bl = blockIdx.x; int d = threadIdx.x;
    float v = A[bl*DD + d];
    __nv_bfloat16 h = __float2bfloat16(v);
    g_a0hi[bl*DD + d] = h;
    g_a0lo[bl*DD + d] = __float2bfloat16(v - __bfloat162float(h));
    v = Bm[bl*DD + d];
    h = __float2bfloat16(v);
    g_bhi[bl*DD + d] = h;
    g_blo[bl*DD + d] = __float2bfloat16(v - __bfloat162float(h));
}

// ---------------- split a*ws2_p into bf16 hi/lo for all p ----------------
__global__ void k_asplit(const float* A) {
    int bl = blockIdx.x; int p = blockIdx.y; int d = threadIdx.x;
    float v = A[bl*DD + d] * g_ws2[p*DD + d];
    __nv_bfloat16 h = __float2bfloat16(v);
    size_t idx = (size_t)(p*NBLL + bl)*DD + d;
    g_ahi[idx] = h;
    g_alo[idx] = __float2bfloat16(v - __bfloat162float(h));
}

// ---------------- plain L2 row norms ----------------
__global__ void k_rownorm(const float* A, const float* Bm) {
    int bl = blockIdx.x; int d = threadIdx.x;
    __shared__ float ra[256], rb[256];
    float av = A[bl*DD+d], bv = Bm[bl*DD+d];
    ra[d] = av*av; rb[d] = bv*bv; __syncthreads();
    for (int o = 128; o; o >>= 1) {
        if (d < o) { ra[d] += ra[d+o]; rb[d] += rb[d+o]; }
        __syncthreads();
    }
    if (d == 0) { g_nra[bl] = sqrtf(ra[0]); g_nrb[bl] = sqrtf(rb[0]); }
}

// ---------------- last-row weighted norms (w1^2) ----------------
__global__ void k_last(const float* A, const float* Bm) {
    int bb = blockIdx.x; int tid = threadIdx.x;
    int w = tid >> 5, lane = tid & 31;
    const float* al = A  + (bb*LL + LL-1)*DD;
    const float* bl_ = Bm + (bb*LL + LL-1)*DD;
    for (int p = w; p < PP; p += 8) {
        float sa = 0.f, sb = 0.f;
        for (int d = lane; d < DD; d += 32) {
            float wv = g_ws1[p*DD+d];
            float av = al[d], bv = bl_[d];
            sa += av*av*wv; sb += bv*bv*wv;
        }
        for (int o = 16; o; o >>= 1) {
            sa += __shfl_down_sync(0xffffffffu, sa, o);
            sb += __shfl_down_sync(0xffffffffu, sb, o);
        }
        if (lane == 0) { g_nal[bb*PP+p] = sqrtf(sa); g_nbl[bb*PP+p] = sqrtf(sb); }
    }
}

// ---------------- weighted norms for cos (w2^2), [p][bl] ----------------
__global__ void k_pnorm(const float* A, const float* Bm) {
    int bl = blockIdx.x; int side = blockIdx.y;
    const float* X = side ? Bm : A;
    float* out = side ? g_nb2 : g_na2;
    __shared__ float sx[DD];
    int tid = threadIdx.x;
    float v = X[bl*DD+tid]; sx[tid] = v*v;
    __syncthreads();
    int w = tid >> 5, lane = tid & 31;
    for (int p = w; p < PP; p += 8) {
        float s = 0.f;
        for (int d = lane; d < DD; d += 32) s += sx[d]*g_ws2[p*DD+d];
        for (int o = 16; o; o >>= 1) s += __shfl_down_sync(0xffffffffu, s, o);
        if (lane == 0) out[p*NBLL + bl] = sqrtf(s);
    }
}

// ---------------- cos tensor via mma.sync bf16 hi/lo (pad-9, hoisted B) ----------------
__global__ __launch_bounds__(256) void k_cos_mma(float* out_ma, float* out_mb) {
    int bb = blockIdx.z, p = blockIdx.y, i0 = blockIdx.x*128;
    int tid = threadIdx.x, w = tid >> 5, lane = tid & 31;
    int g = lane >> 2, tg = lane & 3;
    __shared__ unsigned Ahu[128*9], Alu[128*9];
    __shared__ unsigned Bhu[64*9], Blu[64*9];
    __shared__ float nb_s[512];
    __shared__ float redc[8][64];
    nb_s[tid]       = g_nb2[p*NBLL + bb*LL + tid];
    nb_s[tid + 256] = g_nb2[p*NBLL + bb*LL + tid + 256];
    float na0 = g_na2[p*NBLL + bb*LL + i0 + w*16 + g];
    float na1 = g_na2[p*NBLL + bb*LL + i0 + w*16 + g + 8];
    const __nv_bfloat16* gah = g_ahi + (size_t)(p*NBLL + bb*LL + i0)*DD;
    const __nv_bfloat16* gal = g_alo + (size_t)(p*NBLL + bb*LL + i0)*DD;
    const __nv_bfloat16* gbh = g_bhi + (size_t)(bb*LL)*DD;
    const __nv_bfloat16* gbl = g_blo + (size_t)(bb*LL)*DD;
    float rmax0 = -FLT_MAX, rmax1 = -FLT_MAX;

    #pragma unroll 1
    for (int jt = 0; jt < 8; jt++) {
        int j0 = jt*64;
        float acc[8][4] = {};
        #pragma unroll 1
        for (int kc = 0; kc < 16; kc++) {
            int k0 = kc*16;
            #pragma unroll
            for (int e = 0; e < 4; e++) {
                int idx = tid + e*256; int r = idx >> 3, c2 = idx & 7;
                Ahu[r*9 + c2] = *(const unsigned*)(gah + (size_t)r*DD + k0 + c2*2);
                Alu[r*9 + c2] = *(const unsigned*)(gal + (size_t)r*DD + k0 + c2*2);
            }
            #pragma unroll
            for (int e = 0; e < 2; e++) {
                int idx = tid + e*256; int r = idx >> 3, c2 = idx & 7;
                Bhu[r*9 + c2] = *(const unsigned*)(gbh + (size_t)(j0 + r)*DD + k0 + c2*2);
                Blu[r*9 + c2] = *(const unsigned*)(gbl + (size_t)(j0 + r)*DD + k0 + c2*2);
            }
            __syncthreads();
            unsigned ah[4], alr[4];
            ah[0]  = Ahu[(w*16 + g    )*9 + tg];
            ah[1]  = Ahu[(w*16 + g + 8)*9 + tg];
            ah[2]  = Ahu[(w*16 + g    )*9 + tg + 4];
            ah[3]  = Ahu[(w*16 + g + 8)*9 + tg + 4];
            alr[0] = Alu[(w*16 + g    )*9 + tg];
            alr[1] = Alu[(w*16 + g + 8)*9 + tg];
            alr[2] = Alu[(w*16 + g    )*9 + tg + 4];
            alr[3] = Alu[(w*16 + g + 8)*9 + tg + 4];
            unsigned bh2[16], bl2[16];
            #pragma unroll
            for (int nt = 0; nt < 8; nt++) {
                bh2[2*nt]     = Bhu[(nt*8 + g)*9 + tg];
                bh2[2*nt + 1] = Bhu[(nt*8 + g)*9 + tg + 4];
                bl2[2*nt]     = Blu[(nt*8 + g)*9 + tg];
                bl2[2*nt + 1] = Blu[(nt*8 + g)*9 + tg + 4];
            }
            #pragma unroll
            for (int nt = 0; nt < 8; nt++) {
                mma16816(acc[nt], ah, &bh2[2*nt]);
                mma16816(acc[nt], ah, &bl2[2*nt]);
                mma16816(acc[nt], alr, &bh2[2*nt]);
            }
            __syncthreads();
        }
        // epilogue for this j-tile (R12-proven)
        #pragma unroll
        for (int nt = 0; nt < 8; nt++) {
            int c0 = j0 + nt*8 + tg*2, c1 = c0 + 1;
            float v00 = acc[nt][0] / (na0*nb_s[c0] + EPSF);
            float v01 = acc[nt][1] / (na0*nb_s[c1] + EPSF);
            float v10 = acc[nt][2] / (na1*nb_s[c0] + EPSF);
            float v11 = acc[nt][3] / (na1*nb_s[c1] + EPSF);
            rmax0 = fmaxf(rmax0, fmaxf(v00, v01));
            rmax1 = fmaxf(rmax1, fmaxf(v10, v11));
            float cm0 = fmaxf(v00, v10), cm1 = fmaxf(v01, v11);
            cm0 = fmaxf(cm0, __shfl_xor_sync(0xffffffffu, cm0, 4));
            cm1 = fmaxf(cm1, __shfl_xor_sync(0xffffffffu, cm1, 4));
            cm0 = fmaxf(cm0, __shfl_xor_sync(0xffffffffu, cm0, 8));
            cm1 = fmaxf(cm1, __shfl_xor_sync(0xffffffffu, cm1, 8));
            cm0 = fmaxf(cm0, __shfl_xor_sync(0xffffffffu, cm0, 16));
            cm1 = fmaxf(cm1, __shfl_xor_sync(0xffffffffu, cm1, 16));
            if (g == 0) {
                redc[w][nt*8 + tg*2]     = cm0;
                redc[w][nt*8 + tg*2 + 1] = cm1;
            }
        }
        __syncthreads();
        if (tid < 64) {
            float m = redc[0][tid];
            #pragma unroll
            for (int k = 1; k < 8; k++) m = fmaxf(m, redc[k][tid]);
            atomicMaxF(&out_mb[(bb*LL + j0 + tid)*MF4 + PP + p], m);
        }
        __syncthreads();
    }
    rmax0 = fmaxf(rmax0, __shfl_xor_sync(0xffffffffu, rmax0, 1));
    rmax1 = fmaxf(rmax1, __shfl_xor_sync(0xffffffffu, rmax1, 1));
    rmax0 = fmaxf(rmax0, __shfl_xor_sync(0xffffffffu, rmax0, 2));
    rmax1 = fmaxf(rmax1, __shfl_xor_sync(0xffffffffu, rmax1, 2));
    if (tg == 0) {
        out_ma[(bb*LL + i0 + w*16 + g    )*MF4 + PP + p] = rmax0;
        out_ma[(bb*LL + i0 + w*16 + g + 8)*MF4 + PP + p] = rmax1;
    }
}

// ---------------- raw = a @ b^T via mma.sync bf16 hi/lo (3-term) ----------------
__global__ __launch_bounds__(256) void k_raw_mma() {
    int bb = blockIdx.z, j0 = blockIdx.x*64, i0 = blockIdx.y*128;
    int tid = threadIdx.x, w = tid >> 5, lane = tid & 31;
    int g = lane >> 2, tg = lane & 3;
    __shared__ unsigned Ahu[128*9], Alu[128*9];
    __shared__ unsigned Bhu[64*9], Blu[64*9];
    const __nv_bfloat16* gah = g_a0hi + (size_t)(bb*LL + i0)*DD;
    const __nv_bfloat16* gal = g_a0lo + (size_t)(bb*LL + i0)*DD;
    const __nv_bfloat16* gbh = g_bhi + (size_t)(bb*LL + j0)*DD;
    const __nv_bfloat16* gbl = g_blo + (size_t)(bb*LL + j0)*DD;
    float acc[8][4] = {};
    #pragma unroll 1
    for (int kc = 0; kc < 16; kc++) {
        int k0 = kc*16;
        #pragma unroll
        for (int e = 0; e < 4; e++) {
            int idx = tid + e*256; int r = idx >> 3, c2 = idx & 7;
            Ahu[r*9 + c2] = *(const unsigned*)(gah + (size_t)r*DD + k0 + c2*2);
            Alu[r*9 + c2] = *(const unsigned*)(gal + (size_t)r*DD + k0 + c2*2);
        }
        #pragma unroll
        for (int e = 0; e < 2; e++) {
            int idx = tid + e*256; int r = idx >> 3, c2 = idx & 7;
            Bhu[r*9 + c2] = *(const unsigned*)(gbh + (size_t)r*DD + k0 + c2*2);
            Blu[r*9 + c2] = *(const unsigned*)(gbl + (size_t)r*DD + k0 + c2*2);
        }
        __syncthreads();
        unsigned ah[4], alr[4];
        ah[0]  = Ahu[(w*16 + g    )*9 + tg];
        ah[1]  = Ahu[(w*16 + g + 8)*9 + tg];
        ah[2]  = Ahu[(w*16 + g    )*9 + tg + 4];
        ah[3]  = Ahu[(w*16 + g + 8)*9 + tg + 4];
        alr[0] = Alu[(w*16 + g    )*9 + tg];
        alr[1] = Alu[(w*16 + g + 8)*9 + tg];
        alr[2] = Alu[(w*16 + g    )*9 + tg + 4];
        alr[3] = Alu[(w*16 + g + 8)*9 + tg + 4];
        unsigned bh2[16], bl2[16];
        #pragma unroll
        for (int nt = 0; nt < 8; nt++) {
            bh2[2*nt]     = Bhu[(nt*8 + g)*9 + tg];
            bh2[2*nt + 1] = Bhu[(nt*8 + g)*9 + tg + 4];
            bl2[2*nt]     = Blu[(nt*8 + g)*9 + tg];
            bl2[2*nt + 1] = Blu[(nt*8 + g)*9 + tg + 4];
        }
        #pragma unroll
        for (int nt = 0; nt < 8; nt++) {
            mma16816(acc[nt], ah, &bh2[2*nt]);
            mma16816(acc[nt], ah, &bl2[2*nt]);
            mma16816(acc[nt], alr, &bh2[2*nt]);
        }
        __syncthreads();
    }
    #pragma unroll
    for (int nt = 0; nt < 8; nt++) {
        int gi0 = bb*LL + i0 + w*16 + g, gi1 = gi0 + 8;
        int c0 = j0 + nt*8 + tg*2;
        *(float2*)&g_raw[(size_t)gi0*LL + c0] = make_float2(acc[nt][0], acc[nt][1]);
        *(float2*)&g_raw[(size_t)gi1*LL + c0] = make_float2(acc[nt][2], acc[nt][3]);
    }
}

// ---------------- per-row stats ----------------
__global__ void k_rowstats(const int* ma, const int* mb, const float* temp_p) {
    int bl = blockIdx.x; int bb = bl / LL;
    int tid = threadIdx.x;
    __shared__ float s[LL];
    s[tid]       = g_raw[bl*LL + tid];
    s[tid + 256] = g_raw[bl*LL + tid + 256];
    __syncthreads();
    float temp = temp_p[0];
    int mai = ma[bl];
    float nrai = g_nra[bl];
    float mx = -FLT_MAX, amx = -FLT_MAX, asum = 0.f;
    for (int j = tid; j < LL; j += 256) {
        float rv = s[j];
        float attn = (mai && mb[bb*LL+j]) ? rv*temp : NEGF;
        mx = fmaxf(mx, attn);
        float al = rv / (nrai*g_nrb[bb*LL+j] + EPSF);
        amx = fmaxf(amx, al); asum += al;
    }
    __shared__ float red[256];
    red[tid] = mx; __syncthreads();
    for (int o = 128; o; o >>= 1) { if (tid < o) red[tid] = fmaxf(red[tid], red[tid+o]); __syncthreads(); }
    float MX = red[0]; __syncthreads();
    red[tid] = amx; __syncthreads();
    for (int o = 128; o; o >>= 1) { if (tid < o) red[tid] = fmaxf(red[tid], red[tid+o]); __syncthreads(); }
    float AMX = red[0]; __syncthreads();
    red[tid] = asum; __syncthreads();
    for (int o = 128; o; o >>= 1) { if (tid < o) red[tid] += red[tid+o]; __syncthreads(); }
    float ASUM = red[0]; __syncthreads();
    float se = 0.f;
    for (int j = tid; j < LL; j += 256) {
        float rv = s[j];
        float attn = (mai && mb[bb*LL+j]) ? rv*temp : NEGF;
        se += expf(attn - MX);
    }
    red[tid] = se; __syncthreads();
    for (int o = 128; o; o >>= 1) { if (tid < o) red[tid] += red[tid+o]; __syncthreads(); }
    if (tid == 0) {
        g_rowmax[bl] = MX;
        g_rowsuminv[bl] = 1.0f/red[0];
        g_arowsuminv[bl] = 1.0f/ASUM;
        g_amax2[bl] = AMX;
    }
}

// ---------------- per-col stats ----------------
__global__ void k_colstats(const int* ma, const int* mb, const float* temp_p) {
    int bb = blockIdx.y; int j = blockIdx.x*32 + threadIdx.x;
    int tx = threadIdx.x, ty = threadIdx.y;
    float temp = temp_p[0];
    int mbj = mb[bb*LL+j];
    float nrbj = g_nrb[bb*LL+j];
    float mx = -FLT_MAX, amx = -FLT_MAX, asum = 0.f;
    for (int i = ty; i < LL; i += 8) {
        float rv = g_raw[(bb*LL+i)*LL + j];
        float attn = (ma[bb*LL+i] && mbj) ? rv*temp : NEGF;
        mx = fmaxf(mx, attn);
        float al = rv / (g_nra[bb*LL+i]*nrbj + EPSF);
        amx = fmaxf(amx, al); asum += al;
    }
    __shared__ float r1[8][32], r2[8][32], r3[8][32];
    __shared__ float cm[32], cam[32], cas[32];
    r1[ty][tx] = mx; r2[ty][tx] = amx; r3[ty][tx] = asum;
    __syncthreads();
    if (ty == 0) {
        float m = r1[0][tx], a2 = r2[0][tx], s = r3[0][tx];
        for (int k = 1; k < 8; k++) { m = fmaxf(m, r1[k][tx]); a2 = fmaxf(a2, r2[k][tx]); s += r3[k][tx]; }
        cm[tx] = m; cam[tx] = a2; cas[tx] = s;
    }
    __syncthreads();
    float MX = cm[tx];
    float se = 0.f;
    for (int i = ty; i < LL; i += 8) {
        float rv = g_raw[(bb*LL+i)*LL + j];
        float attn = (ma[bb*LL+i] && mbj) ? rv*temp : NEGF;
        se += expf(attn - MX);
    }
    __syncthreads();
    r1[ty][tx] = se; __syncthreads();
    if (ty == 0) {
        float s = r1[0][tx];
        for (int k = 1; k < 8; k++) s += r1[k][tx];
        int idx = bb*LL+j;
        g_colmax[idx] = MX;
        g_colsuminv[idx] = 1.0f/s;
        g_acolsuminv[idx] = 1.0f/cas[tx];
        g_amax1[idx] = cam[tx];
    }
}

// ---------------- ia / s2_mean : FFMA2 dup-P/Q (proven) ----------------
__global__ __launch_bounds__(256) void k_ab(const float* Bm, const int* ma, const int* mb,
                                            const float* temp_p, float* out_ia) {
    int bb = blockIdx.z; int i0 = blockIdx.x*64; int d0 = blockIdx.y*64;
    int tid = threadIdx.x;
    int tx = tid & 15, ty = tid >> 4;
    float temp = temp_p[0];
    __shared__ float Pd[16][132], Qd[16][132], Bs[16][68];
    u64 accP[4][2] = {}, accQ[4][2] = {};
    for (int k0 = 0; k0 < LL; k0 += 16) {
        #pragma unroll
        for (int e = 0; e < 4; e++) {
            int idx = tid + e*256;
            int r = idx >> 4, c = idx & 15;
            int gi = bb*LL + i0 + r, gj = bb*LL + k0 + c;
            float rv = g_raw[gi*LL + k0 + c];
            float attn = (ma[gi] && mb[gj]) ? rv*temp : NEGF;
            float pv = expf(attn - g_rowmax[gi]) * g_rowsuminv[gi];
            float qv = rv / (g_nra[gi]*g_nrb[gj] + EPSF) * g_arowsuminv[gi];
            *(float2*)&Pd[c][2*r] = make_float2(pv, pv);
            *(float2*)&Qd[c][2*r] = make_float2(qv, qv);
        }
        #pragma unroll
        for (int e = 0; e < 4; e++) {
            int idx = tid + e*256; int r = idx >> 6, c = idx & 63;
            Bs[r][c] = Bm[(bb*LL + k0 + r)*DD + d0 + c];
        }
        __syncthreads();
        #pragma unroll
        for (int kk = 0; kk < 16; kk++) {
            u64 Pr[4], Qr[4], Br[2];
            ulonglong2 t;
            t = *(const ulonglong2*)&Pd[kk][ty*8   ]; Pr[0]=t.x; Pr[1]=t.y;
            t = *(const ulonglong2*)&Pd[kk][ty*8+ 4]; Pr[2]=t.x; Pr[3]=t.y;
            t = *(const ulonglong2*)&Qd[kk][ty*8   ]; Qr[0]=t.x; Qr[1]=t.y;
            t = *(const ulonglong2*)&Qd[kk][ty*8+ 4]; Qr[2]=t.x; Qr[3]=t.y;
            t = *(const ulonglong2*)&Bs[kk][tx*4]; Br[0]=t.x; Br[1]=t.y;
            #pragma unroll
            for (int r = 0; r < 4; r++) {
                ffma2(accP[r][0], Pr[r], Br[0]);
                ffma2(accP[r][1], Pr[r], Br[1]);
                ffma2(accQ[r][0], Qr[r], Br[0]);
                ffma2(accQ[r][1], Qr[r], Br[1]);
            }
        }
        __syncthreads();
    }
    #pragma unroll
    for (int r = 0; r < 4; r++) {
        int gi = bb*LL + i0 + ty*4 + r;
        ulonglong2 vp; vp.x = accP[r][0]; vp.y = accP[r][1];
        ulonglong2 vq; vq.x = accQ[r][0]; vq.y = accQ[r][1];
        *(ulonglong2*)&out_ia[gi*DD + d0 + tx*4] = vp;
        *(ulonglong2*)&g_s2m [gi*DD + d0 + tx*4] = vq;
    }
}

// ---------------- ib / s1_mean : FFMA2 dup-P/Q (proven) ----------------
__global__ __launch_bounds__(256) void k_ba(const float* A, const int* ma, const int* mb,
                                            const float* temp_p, float* out_ib) {
    int bb = blockIdx.z; int j0 = blockIdx.x*64; int d0 = blockIdx.y*64;
    int tid = threadIdx.x;
    int tx = tid & 15, ty = tid >> 4;
    float temp = temp_p[0];
    __shared__ float Pd[16][132], Qd[16][132], As[16][68];
    u64 accP[4][2] = {}, accQ[4][2] = {};
    for (int k0 = 0; k0 < LL; k0 += 16) {
        #pragma unroll
        for (int e = 0; e < 4; e++) {
            int idx = tid + e*256;
            int r = idx >> 6, c = idx & 63;
            int gi = bb*LL + k0 + r, gj = bb*LL + j0 + c;
            float rv = g_raw[gi*LL + j0 + c];
            float attn = (ma[gi] && mb[gj]) ? rv*temp : NEGF;
            float pv = expf(attn - g_colmax[gj]) * g_colsuminv[gj];
            float qv = rv / (g_nra[gi]*g_nrb[gj] + EPSF) * g_acolsuminv[gj];
            *(float2*)&Pd[r][2*c] = make_float2(pv, pv);
            *(float2*)&Qd[r][2*c] = make_float2(qv, qv);
            As[r][c] = A[(bb*LL + k0 + r)*DD + d0 + c];
        }
        __syncthreads();
        #pragma unroll
        for (int kk = 0; kk < 16; kk++) {
            u64 Pr[4], Qr[4], Br[2];
            ulonglong2 t;
            t = *(const ulonglong2*)&Pd[kk][ty*8   ]; Pr[0]=t.x; Pr[1]=t.y;
            t = *(const ulonglong2*)&Pd[kk][ty*8+ 4]; Pr[2]=t.x; Pr[3]=t.y;
            t = *(const ulonglong2*)&Qd[kk][ty*8   ]; Qr[0]=t.x; Qr[1]=t.y;
            t = *(const ulonglong2*)&Qd[kk][ty*8+ 4]; Qr[2]=t.x; Qr[3]=t.y;
            t = *(const ulonglong2*)&As[kk][tx*4]; Br[0]=t.x; Br[1]=t.y;
            #pragma unroll
            for (int r = 0; r < 4; r++) {
                ffma2(accP[r][0], Pr[r], Br[0]);
                ffma2(accP[r][1], Pr[r], Br[1]);
                ffma2(accQ[r][0], Qr[r], Br[0]);
                ffma2(accQ[r][1], Qr[r], Br[1]);
            }
        }
        __syncthreads();
    }
    #pragma unroll
    for (int r = 0; r < 4; r++) {
        int gj = bb*LL + j0 + ty*4 + r;
        ulonglong2 vp; vp.x = accP[r][0]; vp.y = accP[r][1];
        ulonglong2 vq; vq.x = accQ[r][0]; vq.y = accQ[r][1];
        *(ulonglong2*)&out_ib[gj*DD + d0 + tx*4] = vp;
        *(ulonglong2*)&g_s1m [gj*DD + d0 + tx*4] = vq;
    }
}

// ---------------- metrics a ----------------
__global__ void k_metrics_a(const float* A, const float* Bm, float* out_ma) {
    int bl = blockIdx.x; int bb = bl / LL;
    __shared__ float sa[DD], sm[DD], sl[DD];
    int tid = threadIdx.x;
    sa[tid] = A[bl*DD + tid];
    sm[tid] = g_s2m[bl*DD + tid];
    sl[tid] = Bm[(bb*LL + LL-1)*DD + tid];
    __syncthreads();
    float amax = g_amax2[bl];
    int w = tid >> 5, lane = tid & 31;
    for (int p = w; p < PP; p += 8) {
        float s_ab=0.f, s_a1=0.f, s_am=0.f, s_a3=0.f, s_m3=0.f, s_w4=0.f, s_a4=0.f;
        for (int d = lane; d < DD; d += 32) {
            float av = sa[d], mv = sm[d], lv = sl[d];
            float w1v = g_ws1[p*DD+d], w3v = g_ws3[p*DD+d], w4v = g_ws4[p*DD+d];
            s_ab += av*w1v*lv;  s_a1 += av*av*w1v;
            s_am += av*w3v*mv;  s_a3 += av*av*w3v;  s_m3 += mv*mv*w3v;
            s_w4 += av*w4v;     s_a4 += av*av*w4v;
        }
        for (int o = 16; o; o >>= 1) {
            s_ab += __shfl_down_sync(0xffffffffu, s_ab, o);
            s_a1 += __shfl_down_sync(0xffffffffu, s_a1, o);
            s_am += __shfl_down_sync(0xffffffffu, s_am, o);
            s_a3 += __shfl_down_sync(0xffffffffu, s_a3, o);
            s_m3 += __shfl_down_sync(0xffffffffu, s_m3, o);
            s_w4 += __shfl_down_sync(0xffffffffu, s_w4, o);
            s_a4 += __shfl_down_sync(0xffffffffu, s_a4, o);
        }
        if (lane == 0) {
            float* mrow = out_ma + bl*MF4;
            mrow[p]        = s_ab / fmaxf(sqrtf(s_a1)*g_nbl[bb*PP+p], EPSF);
            mrow[2*PP + p] = s_am / fmaxf(sqrtf(s_a3)*sqrtf(s_m3), EPSF);
            mrow[3*PP + p] = amax*s_w4 / fmaxf(sqrtf(s_a4)*fabsf(amax)*g_wn[p], EPSF);
        }
    }
}

// ---------------- metrics b ----------------
__global__ void k_metrics_b(const float* A, const float* Bm, float* out_mb) {
    int bl = blockIdx.x; int bb = bl / LL;
    __shared__ float sb[DD], sm[DD], sl[DD];
    int tid = threadIdx.x;
    sb[tid] = Bm[bl*DD + tid];
    sm[tid] = g_s1m[bl*DD + tid];
    sl[tid] = A[(bb*LL + LL-1)*DD + tid];
    __syncthreads();
    float amax = g_amax1[bl];
    int w = tid >> 5, lane = tid & 31;
    for (int p = w; p < PP; p += 8) {
        float s_ab=0.f, s_b1=0.f, s_am=0.f, s_b3=0.f, s_m3=0.f, s_w4=0.f, s_b4=0.f;
        for (int d = lane; d < DD; d += 32) {
            float bv = sb[d], mv = sm[d], lv = sl[d];
            float w1v = g_ws1[p*DD+d], w3v = g_ws3[p*DD+d], w4v = g_ws4[p*DD+d];
            s_ab += bv*w1v*lv;  s_b1 += bv*bv*w1v;
            s_am += bv*w3v*mv;  s_b3 += bv*bv*w3v;  s_m3 += mv*mv*w3v;
            s_w4 += bv*w4v;     s_b4 += bv*bv*w4v;
        }
        for (int o = 16; o; o >>= 1) {
            s_ab += __shfl_down_sync(0xffffffffu, s_ab, o);
            s_b1 += __shfl_down_sync(0xffffffffu, s_b1, o);
            s_am += __shfl_down_sync(0xffffffffu, s_am, o);
            s_b3 += __shfl_down_sync(0xffffffffu, s_b3, o);
            s_m3 += __shfl_down_sync(0xffffffffu, s_m3, o);
            s_w4 += __shfl_down_sync(0xffffffffu, s_w4, o);
            s_b4 += __shfl_down_sync(0xffffffffu, s_b4, o);
        }
        if (lane == 0) {
            float* mrow = out_mb + bl*MF4;
            mrow[p]        = s_ab / fmaxf(sqrtf(s_b1)*g_nal[bb*PP+p], EPSF);
            mrow[2*PP + p] = s_am / fmaxf(sqrtf(s_b3)*sqrtf(s_m3), EPSF);
            mrow[3*PP + p] = amax*s_w4 / fmaxf(sqrtf(s_b4)*fabsf(amax)*g_wn[p], EPSF);
        }
    }
}

// ---------------- launch ----------------
extern "C" void kernel_launch(void* const* d_in, const int* in_sizes, int n_in,
                              void* d_out, int out_size) {
    const float* a  = (const float*)d_in[0];
    const float* b  = (const float*)d_in[1];
    const int* ma   = (const int*)d_in[2];
    const int* mb   = (const int*)d_in[3];
    const float* w1 = (const float*)d_in[4];
    const float* w2 = (const float*)d_in[5];
    const float* w3 = (const float*)d_in[6];
    const float* w4 = (const float*)d_in[7];
    const float* temp = (const float*)d_in[8];

    float* out = (float*)d_out;
    float* out_ia = out;
    float* out_ib = out + NB*LL*DD;
    float* out_ma = out + 2*NB*LL*DD;
    float* out_mb = out_ma + NB*LL*MF4;

    k_prep<<<PP, 256>>>(w1, w2, w3, w4, out_mb);                      // 0
    k_absplit<<<NBLL, 256>>>(a, b);                                   // 1
    k_asplit<<<dim3(NBLL, PP), 256>>>(a);                             // 2
    k_pnorm<<<dim3(NBLL, 2), 256>>>(a, b);                            // 3
    k_rownorm<<<NBLL, 256>>>(a, b);                                   // 4
    k_cos_mma<<<dim3(LL/128, PP, NB), 256>>>(out_ma, out_mb);         // 5 <- ncu window
    k_raw_mma<<<dim3(LL/64, LL/128, NB), 256>>>();                    // 6
    k_last<<<NB, 256>>>(a, b);                                        // 7
    k_rowstats<<<NBLL, 256>>>(ma, mb, temp);                          // 8
    k_colstats<<<dim3(LL/32, NB), dim3(32,8)>>>(ma, mb, temp);        // 9
    k_ab<<<dim3(LL/64, DD/64, NB), 256>>>(b, ma, mb, temp, out_ia);   // 10
    k_ba<<<dim3(LL/64, DD/64, NB), 256>>>(a, ma, mb, temp, out_ib);   // 11
    k_metrics_a<<<NBLL, 256>>>(a, b, out_ma);                         // 12
    k_metrics_b<<<NBLL, 256>>>(a, b, out_mb);                         // 13
}

// round 14
// speedup vs baseline: 1.0682x; 1.0682x over previous
#include <cuda_runtime.h>
#include <cuda_bf16.h>
#include <float.h>
#include <math.h>

#define LL 512
#define DD 256
#define PP 20
#define NB 16
#define NBLL (NB*LL)
#define EPSF 1e-8f
#define NEGF -10000000.0f
#define MF4 (4*PP)

typedef unsigned long long u64;

__device__ __forceinline__ void ffma2(u64 &d, u64 a, u64 b) {
    asm("fma.rn.f32x2 %0, %1, %2, %0;" : "+l"(d) : "l"(a), "l"(b));
}
// warp-level bf16 tensor-core MMA (sm_80+, plain target)
__device__ __forceinline__ void mma16816(float* c, const unsigned* a, const unsigned* b) {
    asm volatile("mma.sync.aligned.m16n8k16.row.col.f32.bf16.bf16.f32 "
        "{%0,%1,%2,%3}, {%4,%5,%6,%7}, {%8,%9}, {%0,%1,%2,%3};"
        : "+f"(c[0]), "+f"(c[1]), "+f"(c[2]), "+f"(c[3])
        : "r"(a[0]), "r"(a[1]), "r"(a[2]), "r"(a[3]), "r"(b[0]), "r"(b[1]));
}

// ---------------- device scratch (allocation-free) ----------------
static __device__ float g_raw[NB*LL*LL];
static __device__ __nv_bfloat16 g_ahi[PP*NBLL*DD];   // (a*ws2_p) hi
static __device__ __nv_bfloat16 g_alo[PP*NBLL*DD];   // (a*ws2_p) lo
static __device__ __nv_bfloat16 g_bhi[NBLL*DD];
static __device__ __nv_bfloat16 g_blo[NBLL*DD];
static __device__ float g_s2m[NB*LL*DD];
static __device__ float g_s1m[NB*LL*DD];
static __device__ float g_nra[NBLL];
static __device__ float g_nrb[NBLL];
static __device__ float g_rowmax[NBLL];
static __device__ float g_rowsuminv[NBLL];
static __device__ float g_arowsuminv[NBLL];
static __device__ float g_amax2[NBLL];
static __device__ float g_colmax[NBLL];
static __device__ float g_colsuminv[NBLL];
static __device__ float g_acolsuminv[NBLL];
static __device__ float g_amax1[NBLL];
static __device__ float g_na2[PP*NBLL];   // [p][bl]
static __device__ float g_nb2[PP*NBLL];   // [p][bl]
static __device__ float g_ws1[PP*DD];
static __device__ float g_ws2[PP*DD];
static __device__ float g_ws3[PP*DD];
static __device__ float g_ws4[PP*DD];
static __device__ float g_nbl[NB*PP];
static __device__ float g_nal[NB*PP];
static __device__ float g_wn[PP];

__device__ __forceinline__ void atomicMaxF(float* addr, float v) {
    int old = __float_as_int(*addr);
    while (__int_as_float(old) < v) {
        int prev = atomicCAS((int*)addr, old, __float_as_int(v));
        if (prev == old) break;
        old = prev;
    }
}

// ---------------- prep: squared weights + wn + mm_b init ----------------
__global__ void k_prep(const float* w1, const float* w2, const float* w3, const float* w4,
                       float* out_mb) {
    int p = blockIdx.x, d = threadIdx.x;
    float v1 = w1[p*DD+d]; g_ws1[p*DD+d] = v1*v1;
    float v2 = w2[p*DD+d]; g_ws2[p*DD+d] = v2*v2;
    float v3 = w3[p*DD+d]; g_ws3[p*DD+d] = v3*v3;
    float v4 = w4[p*DD+d]; float s4 = v4*v4; g_ws4[p*DD+d] = s4;
    __shared__ float red[256];
    red[d] = s4; __syncthreads();
    for (int o = 128; o; o >>= 1) { if (d < o) red[d] += red[d+o]; __syncthreads(); }
    if (d == 0) g_wn[p] = sqrtf(red[0]);
    for (int idx = blockIdx.x*256 + d; idx < NB*LL*PP; idx += PP*256) {
        int bl = idx / PP, pp = idx % PP;
        out_mb[bl*MF4 + PP + pp] = -FLT_MAX;
    }
}

// ---------------- splits: p<PP -> a*ws2_p hi/lo ; p==PP -> b hi/lo ----------------
__global__ void k_split(const float* A, const float* Bm) {
    int bl = blockIdx.x; int p = blockIdx.y; int d = threadIdx.x;
    if (p < PP) {
        float v = A[bl*DD + d] * g_ws2[p*DD + d];
        __nv_bfloat16 h = __float2bfloat16(v);
        size_t idx = (size_t)(p*NBLL + bl)*DD + d;
        g_ahi[idx] = h;
        g_alo[idx] = __float2bfloat16(v - __bfloat162float(h));
    } else {
        float v = Bm[bl*DD + d];
        __nv_bfloat16 h = __float2bfloat16(v);
        g_bhi[bl*DD + d] = h;
        g_blo[bl*DD + d] = __float2bfloat16(v - __bfloat162float(h));
    }
}

// ---------------- plain L2 row norms ----------------
__global__ void k_rownorm(const float* A, const float* Bm) {
    int bl = blockIdx.x; int d = threadIdx.x;
    __shared__ float ra[256], rb[256];
    float av = A[bl*DD+d], bv = Bm[bl*DD+d];
    ra[d] = av*av; rb[d] = bv*bv; __syncthreads();
    for (int o = 128; o; o >>= 1) {
        if (d < o) { ra[d] += ra[d+o]; rb[d] += rb[d+o]; }
        __syncthreads();
    }
    if (d == 0) { g_nra[bl] = sqrtf(ra[0]); g_nrb[bl] = sqrtf(rb[0]); }
}

// ---------------- last-row weighted norms (w1^2) ----------------
__global__ void k_last(const float* A, const float* Bm) {
    int bb = blockIdx.x; int tid = threadIdx.x;
    int w = tid >> 5, lane = tid & 31;
    const float* al = A  + (bb*LL + LL-1)*DD;
    const float* bl_ = Bm + (bb*LL + LL-1)*DD;
    for (int p = w; p < PP; p += 8) {
        float sa = 0.f, sb = 0.f;
        for (int d = lane; d < DD; d += 32) {
            float wv = g_ws1[p*DD+d];
            float av = al[d], bv = bl_[d];
            sa += av*av*wv; sb += bv*bv*wv;
        }
        for (int o = 16; o; o >>= 1) {
            sa += __shfl_down_sync(0xffffffffu, sa, o);
            sb += __shfl_down_sync(0xffffffffu, sb, o);
        }
        if (lane == 0) { g_nal[bb*PP+p] = sqrtf(sa); g_nbl[bb*PP+p] = sqrtf(sb); }
    }
}

// ---------------- weighted norms for cos (w2^2), [p][bl] ----------------
__global__ void k_pnorm(const float* A, const float* Bm) {
    int bl = blockIdx.x; int side = blockIdx.y;
    const float* X = side ? Bm : A;
    float* out = side ? g_nb2 : g_na2;
    __shared__ float sx[DD];
    int tid = threadIdx.x;
    float v = X[bl*DD+tid]; sx[tid] = v*v;
    __syncthreads();
    int w = tid >> 5, lane = tid & 31;
    for (int p = w; p < PP; p += 8) {
        float s = 0.f;
        for (int d = lane; d < DD; d += 32) s += sx[d]*g_ws2[p*DD+d];
        for (int o = 16; o; o >>= 1) s += __shfl_down_sync(0xffffffffu, s, o);
        if (lane == 0) out[p*NBLL + bl] = sqrtf(s);
    }
}

// ---------------- cos tensor via mma.sync bf16 hi/lo (pad-9, inline B) ----------------
__global__ __launch_bounds__(256) void k_cos_mma(float* out_ma, float* out_mb) {
    int bb = blockIdx.z, p = blockIdx.y, i0 = blockIdx.x*128;
    int tid = threadIdx.x, w = tid >> 5, lane = tid & 31;
    int g = lane >> 2, tg = lane & 3;
    __shared__ unsigned Ahu[128*9], Alu[128*9];
    __shared__ unsigned Bhu[64*9], Blu[64*9];
    __shared__ float nb_s[512];
    __shared__ float redc[8][64];
    nb_s[tid]       = g_nb2[p*NBLL + bb*LL + tid];
    nb_s[tid + 256] = g_nb2[p*NBLL + bb*LL + tid + 256];
    float na0 = g_na2[p*NBLL + bb*LL + i0 + w*16 + g];
    float na1 = g_na2[p*NBLL + bb*LL + i0 + w*16 + g + 8];
    const __nv_bfloat16* gah = g_ahi + (size_t)(p*NBLL + bb*LL + i0)*DD;
    const __nv_bfloat16* gal = g_alo + (size_t)(p*NBLL + bb*LL + i0)*DD;
    const __nv_bfloat16* gbh = g_bhi + (size_t)(bb*LL)*DD;
    const __nv_bfloat16* gbl = g_blo + (size_t)(bb*LL)*DD;
    float rmax0 = -FLT_MAX, rmax1 = -FLT_MAX;

    #pragma unroll 1
    for (int jt = 0; jt < 8; jt++) {
        int j0 = jt*64;
        float acc[8][4] = {};
        #pragma unroll 1
        for (int kc = 0; kc < 16; kc++) {
            int k0 = kc*16;
            #pragma unroll
            for (int e = 0; e < 4; e++) {
                int idx = tid + e*256; int r = idx >> 3, c2 = idx & 7;
                Ahu[r*9 + c2] = *(const unsigned*)(gah + (size_t)r*DD + k0 + c2*2);
                Alu[r*9 + c2] = *(const unsigned*)(gal + (size_t)r*DD + k0 + c2*2);
            }
            #pragma unroll
            for (int e = 0; e < 2; e++) {
                int idx = tid + e*256; int r = idx >> 3, c2 = idx & 7;
                Bhu[r*9 + c2] = *(const unsigned*)(gbh + (size_t)(j0 + r)*DD + k0 + c2*2);
                Blu[r*9 + c2] = *(const unsigned*)(gbl + (size_t)(j0 + r)*DD + k0 + c2*2);
            }
            __syncthreads();
            unsigned ah[4], alr[4];
            ah[0]  = Ahu[(w*16 + g    )*9 + tg];
            ah[1]  = Ahu[(w*16 + g + 8)*9 + tg];
            ah[2]  = Ahu[(w*16 + g    )*9 + tg + 4];
            ah[3]  = Ahu[(w*16 + g + 8)*9 + tg + 4];
            alr[0] = Alu[(w*16 + g    )*9 + tg];
            alr[1] = Alu[(w*16 + g + 8)*9 + tg];
            alr[2] = Alu[(w*16 + g    )*9 + tg + 4];
            alr[3] = Alu[(w*16 + g + 8)*9 + tg + 4];
            #pragma unroll
            for (int nt = 0; nt < 8; nt++) {
                unsigned bh[2], blr[2];
                bh[0]  = Bhu[(nt*8 + g)*9 + tg];
                bh[1]  = Bhu[(nt*8 + g)*9 + tg + 4];
                blr[0] = Blu[(nt*8 + g)*9 + tg];
                blr[1] = Blu[(nt*8 + g)*9 + tg + 4];
                mma16816(acc[nt], ah, bh);
                mma16816(acc[nt], ah, blr);
                mma16816(acc[nt], alr, bh);
            }
            __syncthreads();
        }
        // epilogue for this j-tile (R12-proven)
        #pragma unroll
        for (int nt = 0; nt < 8; nt++) {
            int c0 = j0 + nt*8 + tg*2, c1 = c0 + 1;
            float v00 = acc[nt][0] / (na0*nb_s[c0] + EPSF);
            float v01 = acc[nt][1] / (na0*nb_s[c1] + EPSF);
            float v10 = acc[nt][2] / (na1*nb_s[c0] + EPSF);
            float v11 = acc[nt][3] / (na1*nb_s[c1] + EPSF);
            rmax0 = fmaxf(rmax0, fmaxf(v00, v01));
            rmax1 = fmaxf(rmax1, fmaxf(v10, v11));
            float cm0 = fmaxf(v00, v10), cm1 = fmaxf(v01, v11);
            cm0 = fmaxf(cm0, __shfl_xor_sync(0xffffffffu, cm0, 4));
            cm1 = fmaxf(cm1, __shfl_xor_sync(0xffffffffu, cm1, 4));
            cm0 = fmaxf(cm0, __shfl_xor_sync(0xffffffffu, cm0, 8));
            cm1 = fmaxf(cm1, __shfl_xor_sync(0xffffffffu, cm1, 8));
            cm0 = fmaxf(cm0, __shfl_xor_sync(0xffffffffu, cm0, 16));
            cm1 = fmaxf(cm1, __shfl_xor_sync(0xffffffffu, cm1, 16));
            if (g == 0) {
                redc[w][nt*8 + tg*2]     = cm0;
                redc[w][nt*8 + tg*2 + 1] = cm1;
            }
        }
        __syncthreads();
        if (tid < 64) {
            float m = redc[0][tid];
            #pragma unroll
            for (int k = 1; k < 8; k++) m = fmaxf(m, redc[k][tid]);
            atomicMaxF(&out_mb[(bb*LL + j0 + tid)*MF4 + PP + p], m);
        }
        __syncthreads();
    }
    rmax0 = fmaxf(rmax0, __shfl_xor_sync(0xffffffffu, rmax0, 1));
    rmax1 = fmaxf(rmax1, __shfl_xor_sync(0xffffffffu, rmax1, 1));
    rmax0 = fmaxf(rmax0, __shfl_xor_sync(0xffffffffu, rmax0, 2));
    rmax1 = fmaxf(rmax1, __shfl_xor_sync(0xffffffffu, rmax1, 2));
    if (tg == 0) {
        out_ma[(bb*LL + i0 + w*16 + g    )*MF4 + PP + p] = rmax0;
        out_ma[(bb*LL + i0 + w*16 + g + 8)*MF4 + PP + p] = rmax1;
    }
}

// ---------------- raw = a @ b^T : FFMA2 A-dup + register-prefetch (R10-proven) ----------------
__global__ __launch_bounds__(256, 2) void k_gemm_raw(const float* A, const float* Bm) {
    int bb = blockIdx.z; int i0 = blockIdx.y*128; int j0 = blockIdx.x*64;
    int tid = threadIdx.x;
    int tx = tid & 15, ty = tid >> 4;
    __shared__ float Ad[2][16][260];
    __shared__ float Bs[16][68];
    const int c_ld = tid & 15;
    const int r_ld = tid >> 4;
    u64 acc[8][2] = {};
    float pa[8], pb[4];
    #pragma unroll
    for (int e = 0; e < 8; e++)
        pa[e] = A[(bb*LL + i0 + r_ld + e*16)*DD + c_ld];
    #pragma unroll
    for (int e = 0; e < 4; e++)
        pb[e] = Bm[(bb*LL + j0 + r_ld + e*16)*DD + c_ld];
    #pragma unroll
    for (int e = 0; e < 8; e++)
        *(float2*)&Ad[0][c_ld][2*(r_ld + e*16)] = make_float2(pa[e], pa[e]);
    #pragma unroll
    for (int e = 0; e < 4; e++)
        Bs[c_ld][r_ld + e*16] = pb[e];

    #pragma unroll 1
    for (int s = 0; s < 16; s++) {
        int buf = s & 1;
        __syncthreads();
        if (s + 1 < 16) {
            int k0n = (s + 1) * 16;
            #pragma unroll
            for (int e = 0; e < 8; e++)
                pa[e] = A[(bb*LL + i0 + r_ld + e*16)*DD + k0n + c_ld];
            #pragma unroll
            for (int e = 0; e < 4; e++)
                pb[e] = Bm[(bb*LL + j0 + r_ld + e*16)*DD + k0n + c_ld];
        }
        #pragma unroll
        for (int kk = 0; kk < 16; kk++) {
            u64 Ar[8], Br[2];
            ulonglong2 t;
            t = *(const ulonglong2*)&Ad[buf][kk][ty*16   ]; Ar[0]=t.x; Ar[1]=t.y;
            t = *(const ulonglong2*)&Ad[buf][kk][ty*16+ 4]; Ar[2]=t.x; Ar[3]=t.y;
            t = *(const ulonglong2*)&Ad[buf][kk][ty*16+ 8]; Ar[4]=t.x; Ar[5]=t.y;
            t = *(const ulonglong2*)&Ad[buf][kk][ty*16+12]; Ar[6]=t.x; Ar[7]=t.y;
            t = *(const ulonglong2*)&Bs[kk][tx*4]; Br[0]=t.x; Br[1]=t.y;
            #pragma unroll
            for (int r = 0; r < 8; r++) {
                ffma2(acc[r][0], Ar[r], Br[0]);
                ffma2(acc[r][1], Ar[r], Br[1]);
            }
        }
        __syncthreads();
        if (s + 1 < 16) {
            #pragma unroll
            for (int e = 0; e < 8; e++)
                *(float2*)&Ad[buf^1][c_ld][2*(r_ld + e*16)] = make_float2(pa[e], pa[e]);
            #pragma unroll
            for (int e = 0; e < 4; e++)
                Bs[c_ld][r_ld + e*16] = pb[e];
        }
    }
    #pragma unroll
    for (int r = 0; r < 8; r++) {
        ulonglong2 v; v.x = acc[r][0]; v.y = acc[r][1];
        *(ulonglong2*)&g_raw[(bb*LL + i0 + ty*8 + r)*LL + j0 + tx*4] = v;
    }
}

// ---------------- per-row stats ----------------
__global__ void k_rowstats(const int* ma, const int* mb, const float* temp_p) {
    int bl = blockIdx.x; int bb = bl / LL;
    int tid = threadIdx.x;
    __shared__ float s[LL];
    s[tid]       = g_raw[bl*LL + tid];
    s[tid + 256] = g_raw[bl*LL + tid + 256];
    __syncthreads();
    float temp = temp_p[0];
    int mai = ma[bl];
    float nrai = g_nra[bl];
    float mx = -FLT_MAX, amx = -FLT_MAX, asum = 0.f;
    for (int j = tid; j < LL; j += 256) {
        float rv = s[j];
        float attn = (mai && mb[bb*LL+j]) ? rv*temp : NEGF;
        mx = fmaxf(mx, attn);
        float al = rv / (nrai*g_nrb[bb*LL+j] + EPSF);
        amx = fmaxf(amx, al); asum += al;
    }
    __shared__ float red[256];
    red[tid] = mx; __syncthreads();
    for (int o = 128; o; o >>= 1) { if (tid < o) red[tid] = fmaxf(red[tid], red[tid+o]); __syncthreads(); }
    float MX = red[0]; __syncthreads();
    red[tid] = amx; __syncthreads();
    for (int o = 128; o; o >>= 1) { if (tid < o) red[tid] = fmaxf(red[tid], red[tid+o]); __syncthreads(); }
    float AMX = red[0]; __syncthreads();
    red[tid] = asum; __syncthreads();
    for (int o = 128; o; o >>= 1) { if (tid < o) red[tid] += red[tid+o]; __syncthreads(); }
    float ASUM = red[0]; __syncthreads();
    float se = 0.f;
    for (int j = tid; j < LL; j += 256) {
        float rv = s[j];
        float attn = (mai && mb[bb*LL+j]) ? rv*temp : NEGF;
        se += expf(attn - MX);
    }
    red[tid] = se; __syncthreads();
    for (int o = 128; o; o >>= 1) { if (tid < o) red[tid] += red[tid+o]; __syncthreads(); }
    if (tid == 0) {
        g_rowmax[bl] = MX;
        g_rowsuminv[bl] = 1.0f/red[0];
        g_arowsuminv[bl] = 1.0f/ASUM;
        g_amax2[bl] = AMX;
    }
}

// ---------------- per-col stats ----------------
__global__ void k_colstats(const int* ma, const int* mb, const float* temp_p) {
    int bb = blockIdx.y; int j = blockIdx.x*32 + threadIdx.x;
    int tx = threadIdx.x, ty = threadIdx.y;
    float temp = temp_p[0];
    int mbj = mb[bb*LL+j];
    float nrbj = g_nrb[bb*LL+j];
    float mx = -FLT_MAX, amx = -FLT_MAX, asum = 0.f;
    for (int i = ty; i < LL; i += 8) {
        float rv = g_raw[(bb*LL+i)*LL + j];
        float attn = (ma[bb*LL+i] && mbj) ? rv*temp : NEGF;
        mx = fmaxf(mx, attn);
        float al = rv / (g_nra[bb*LL+i]*nrbj + EPSF);
        amx = fmaxf(amx, al); asum += al;
    }
    __shared__ float r1[8][32], r2[8][32], r3[8][32];
    __shared__ float cm[32], cam[32], cas[32];
    r1[ty][tx] = mx; r2[ty][tx] = amx; r3[ty][tx] = asum;
    __syncthreads();
    if (ty == 0) {
        float m = r1[0][tx], a2 = r2[0][tx], s = r3[0][tx];
        for (int k = 1; k < 8; k++) { m = fmaxf(m, r1[k][tx]); a2 = fmaxf(a2, r2[k][tx]); s += r3[k][tx]; }
        cm[tx] = m; cam[tx] = a2; cas[tx] = s;
    }
    __syncthreads();
    float MX = cm[tx];
    float se = 0.f;
    for (int i = ty; i < LL; i += 8) {
        float rv = g_raw[(bb*LL+i)*LL + j];
        float attn = (ma[bb*LL+i] && mbj) ? rv*temp : NEGF;
        se += expf(attn - MX);
    }
    __syncthreads();
    r1[ty][tx] = se; __syncthreads();
    if (ty == 0) {
        float s = r1[0][tx];
        for (int k = 1; k < 8; k++) s += r1[k][tx];
        int idx = bb*LL+j;
        g_colmax[idx] = MX;
        g_colsuminv[idx] = 1.0f/s;
        g_acolsuminv[idx] = 1.0f/cas[tx];
        g_amax1[idx] = cam[tx];
    }
}

// ---------------- ia / s2_mean : FFMA2 dup-P/Q (proven) ----------------
__global__ __launch_bounds__(256) void k_ab(const float* Bm, const int* ma, const int* mb,
                                            const float* temp_p, float* out_ia) {
    int bb = blockIdx.z; int i0 = blockIdx.x*64; int d0 = blockIdx.y*64;
    int tid = threadIdx.x;
    int tx = tid & 15, ty = tid >> 4;
    float temp = temp_p[0];
    __shared__ float Pd[16][132], Qd[16][132], Bs[16][68];
    u64 accP[4][2] = {}, accQ[4][2] = {};
    for (int k0 = 0; k0 < LL; k0 += 16) {
        #pragma unroll
        for (int e = 0; e < 4; e++) {
            int idx = tid + e*256;
            int r = idx >> 4, c = idx & 15;
            int gi = bb*LL + i0 + r, gj = bb*LL + k0 + c;
            float rv = g_raw[gi*LL + k0 + c];
            float attn = (ma[gi] && mb[gj]) ? rv*temp : NEGF;
            float pv = expf(attn - g_rowmax[gi]) * g_rowsuminv[gi];
            float qv = rv / (g_nra[gi]*g_nrb[gj] + EPSF) * g_arowsuminv[gi];
            *(float2*)&Pd[c][2*r] = make_float2(pv, pv);
            *(float2*)&Qd[c][2*r] = make_float2(qv, qv);
        }
        #pragma unroll
        for (int e = 0; e < 4; e++) {
            int idx = tid + e*256; int r = idx >> 6, c = idx & 63;
            Bs[r][c] = Bm[(bb*LL + k0 + r)*DD + d0 + c];
        }
        __syncthreads();
        #pragma unroll
        for (int kk = 0; kk < 16; kk++) {
            u64 Pr[4], Qr[4], Br[2];
            ulonglong2 t;
            t = *(const ulonglong2*)&Pd[kk][ty*8   ]; Pr[0]=t.x; Pr[1]=t.y;
            t = *(const ulonglong2*)&Pd[kk][ty*8+ 4]; Pr[2]=t.x; Pr[3]=t.y;
            t = *(const ulonglong2*)&Qd[kk][ty*8   ]; Qr[0]=t.x; Qr[1]=t.y;
            t = *(const ulonglong2*)&Qd[kk][ty*8+ 4]; Qr[2]=t.x; Qr[3]=t.y;
            t = *(const ulonglong2*)&Bs[kk][tx*4]; Br[0]=t.x; Br[1]=t.y;
            #pragma unroll
            for (int r = 0; r < 4; r++) {
                ffma2(accP[r][0], Pr[r], Br[0]);
                ffma2(accP[r][1], Pr[r], Br[1]);
                ffma2(accQ[r][0], Qr[r], Br[0]);
                ffma2(accQ[r][1], Qr[r], Br[1]);
            }
        }
        __syncthreads();
    }
    #pragma unroll
    for (int r = 0; r < 4; r++) {
        int gi = bb*LL + i0 + ty*4 + r;
        ulonglong2 vp; vp.x = accP[r][0]; vp.y = accP[r][1];
        ulonglong2 vq; vq.x = accQ[r][0]; vq.y = accQ[r][1];
        *(ulonglong2*)&out_ia[gi*DD + d0 + tx*4] = vp;
        *(ulonglong2*)&g_s2m [gi*DD + d0 + tx*4] = vq;
    }
}

// ---------------- ib / s1_mean : FFMA2 dup-P/Q (proven) ----------------
__global__ __launch_bounds__(256) void k_ba(const float* A, const int* ma, const int* mb,
                                            const float* temp_p, float* out_ib) {
    int bb = blockIdx.z; int j0 = blockIdx.x*64; int d0 = blockIdx.y*64;
    int tid = threadIdx.x;
    int tx = tid & 15, ty = tid >> 4;
    float temp = temp_p[0];
    __shared__ float Pd[16][132], Qd[16][132], As[16][68];
    u64 accP[4][2] = {}, accQ[4][2] = {};
    for (int k0 = 0; k0 < LL; k0 += 16) {
        #pragma unroll
        for (int e = 0; e < 4; e++) {
            int idx = tid + e*256;
            int r = idx >> 6, c = idx & 63;
            int gi = bb*LL + k0 + r, gj = bb*LL + j0 + c;
            float rv = g_raw[gi*LL + j0 + c];
            float attn = (ma[gi] && mb[gj]) ? rv*temp : NEGF;
            float pv = expf(attn - g_colmax[gj]) * g_colsuminv[gj];
            float qv = rv / (g_nra[gi]*g_nrb[gj] + EPSF) * g_acolsuminv[gj];
            *(float2*)&Pd[r][2*c] = make_float2(pv, pv);
            *(float2*)&Qd[r][2*c] = make_float2(qv, qv);
            As[r][c] = A[(bb*LL + k0 + r)*DD + d0 + c];
        }
        __syncthreads();
        #pragma unroll
        for (int kk = 0; kk < 16; kk++) {
            u64 Pr[4], Qr[4], Br[2];
            ulonglong2 t;
            t = *(const ulonglong2*)&Pd[kk][ty*8   ]; Pr[0]=t.x; Pr[1]=t.y;
            t = *(const ulonglong2*)&Pd[kk][ty*8+ 4]; Pr[2]=t.x; Pr[3]=t.y;
            t = *(const ulonglong2*)&Qd[kk][ty*8   ]; Qr[0]=t.x; Qr[1]=t.y;
            t = *(const ulonglong2*)&Qd[kk][ty*8+ 4]; Qr[2]=t.x; Qr[3]=t.y;
            t = *(const ulonglong2*)&As[kk][tx*4]; Br[0]=t.x; Br[1]=t.y;
            #pragma unroll
            for (int r = 0; r < 4; r++) {
                ffma2(accP[r][0], Pr[r], Br[0]);
                ffma2(accP[r][1], Pr[r], Br[1]);
                ffma2(accQ[r][0], Qr[r], Br[0]);
                ffma2(accQ[r][1], Qr[r], Br[1]);
            }
        }
        __syncthreads();
    }
    #pragma unroll
    for (int r = 0; r < 4; r++) {
        int gj = bb*LL + j0 + ty*4 + r;
        ulonglong2 vp; vp.x = accP[r][0]; vp.y = accP[r][1];
        ulonglong2 vq; vq.x = accQ[r][0]; vq.y = accQ[r][1];
        *(ulonglong2*)&out_ib[gj*DD + d0 + tx*4] = vp;
        *(ulonglong2*)&g_s1m [gj*DD + d0 + tx*4] = vq;
    }
}

// ---------------- metrics a ----------------
__global__ void k_metrics_a(const float* A, const float* Bm, float* out_ma) {
    int bl = blockIdx.x; int bb = bl / LL;
    __shared__ float sa[DD], sm[DD], sl[DD];
    int tid = threadIdx.x;
    sa[tid] = A[bl*DD + tid];
    sm[tid] = g_s2m[bl*DD + tid];
    sl[tid] = Bm[(bb*LL + LL-1)*DD + tid];
    __syncthreads();
    float amax = g_amax2[bl];
    int w = tid >> 5, lane = tid & 31;
    for (int p = w; p < PP; p += 8) {
        float s_ab=0.f, s_a1=0.f, s_am=0.f, s_a3=0.f, s_m3=0.f, s_w4=0.f, s_a4=0.f;
        for (int d = lane; d < DD; d += 32) {
            float av = sa[d], mv = sm[d], lv = sl[d];
            float w1v = g_ws1[p*DD+d], w3v = g_ws3[p*DD+d], w4v = g_ws4[p*DD+d];
            s_ab += av*w1v*lv;  s_a1 += av*av*w1v;
            s_am += av*w3v*mv;  s_a3 += av*av*w3v;  s_m3 += mv*mv*w3v;
            s_w4 += av*w4v;     s_a4 += av*av*w4v;
        }
        for (int o = 16; o; o >>= 1) {
            s_ab += __shfl_down_sync(0xffffffffu, s_ab, o);
            s_a1 += __shfl_down_sync(0xffffffffu, s_a1, o);
            s_am += __shfl_down_sync(0xffffffffu, s_am, o);
            s_a3 += __shfl_down_sync(0xffffffffu, s_a3, o);
            s_m3 += __shfl_down_sync(0xffffffffu, s_m3, o);
            s_w4 += __shfl_down_sync(0xffffffffu, s_w4, o);
            s_a4 += __shfl_down_sync(0xffffffffu, s_a4, o);
        }
        if (lane == 0) {
            float* mrow = out_ma + bl*MF4;
            mrow[p]        = s_ab / fmaxf(sqrtf(s_a1)*g_nbl[bb*PP+p], EPSF);
            mrow[2*PP + p] = s_am / fmaxf(sqrtf(s_a3)*sqrtf(s_m3), EPSF);
            mrow[3*PP + p] = amax*s_w4 / fmaxf(sqrtf(s_a4)*fabsf(amax)*g_wn[p], EPSF);
        }
    }
}

// ---------------- metrics b ----------------
__global__ void k_metrics_b(const float* A, const float* Bm, float* out_mb) {
    int bl = blockIdx.x; int bb = bl / LL;
    __shared__ float sb[DD], sm[DD], sl[DD];
    int tid = threadIdx.x;
    sb[tid] = Bm[bl*DD + tid];
    sm[tid] = g_s1m[bl*DD + tid];
    sl[tid] = A[(bb*LL + LL-1)*DD + tid];
    __syncthreads();
    float amax = g_amax1[bl];
    int w = tid >> 5, lane = tid & 31;
    for (int p = w; p < PP; p += 8) {
        float s_ab=0.f, s_b1=0.f, s_am=0.f, s_b3=0.f, s_m3=0.f, s_w4=0.f, s_b4=0.f;
        for (int d = lane; d < DD; d += 32) {
            float bv = sb[d], mv = sm[d], lv = sl[d];
            float w1v = g_ws1[p*DD+d], w3v = g_ws3[p*DD+d], w4v = g_ws4[p*DD+d];
            s_ab += bv*w1v*lv;  s_b1 += bv*bv*w1v;
            s_am += bv*w3v*mv;  s_b3 += bv*bv*w3v;  s_m3 += mv*mv*w3v;
            s_w4 += bv*w4v;     s_b4 += bv*bv*w4v;
        }
        for (int o = 16; o; o >>= 1) {
            s_ab += __shfl_down_sync(0xffffffffu, s_ab, o);
            s_b1 += __shfl_down_sync(0xffffffffu, s_b1, o);
            s_am += __shfl_down_sync(0xffffffffu, s_am, o);
            s_b3 += __shfl_down_sync(0xffffffffu, s_b3, o);
            s_m3 += __shfl_down_sync(0xffffffffu, s_m3, o);
            s_w4 += __shfl_down_sync(0xffffffffu, s_w4, o);
            s_b4 += __shfl_down_sync(0xffffffffu, s_b4, o);
        }
        if (lane == 0) {
            float* mrow = out_mb + bl*MF4;
            mrow[p]        = s_ab / fmaxf(sqrtf(s_b1)*g_nal[bb*PP+p], EPSF);
            mrow[2*PP + p] = s_am / fmaxf(sqrtf(s_b3)*sqrtf(s_m3), EPSF);
            mrow[3*PP + p] = amax*s_w4 / fmaxf(sqrtf(s_b4)*fabsf(amax)*g_wn[p], EPSF);
        }
    }
}

// ---------------- launch (k_cos_mma at index 3 for the ncu window) ----------------
extern "C" void kernel_launch(void* const* d_in, const int* in_sizes, int n_in,
                              void* d_out, int out_size) {
    const float* a  = (const float*)d_in[0];
    const float* b  = (const float*)d_in[1];
    const int* ma   = (const int*)d_in[2];
    const int* mb   = (const int*)d_in[3];
    const float* w1 = (const float*)d_in[4];
    const float* w2 = (const float*)d_in[5];
    const float* w3 = (const float*)d_in[6];
    const float* w4 = (const float*)d_in[7];
    const float* temp = (const float*)d_in[8];

    float* out = (float*)d_out;
    float* out_ia = out;
    float* out_ib = out + NB*LL*DD;
    float* out_ma = out + 2*NB*LL*DD;
    float* out_mb = out_ma + NB*LL*MF4;

    k_prep<<<PP, 256>>>(w1, w2, w3, w4, out_mb);                      // 0
    k_split<<<dim3(NBLL, PP+1), 256>>>(a, b);                         // 1
    k_pnorm<<<dim3(NBLL, 2), 256>>>(a, b);                            // 2
    k_cos_mma<<<dim3(LL/128, PP, NB), 256>>>(out_ma, out_mb);         // 3 <- ncu window
    k_rownorm<<<NBLL, 256>>>(a, b);                                   // 4
    k_gemm_raw<<<dim3(LL/64, LL/128, NB), 256>>>(a, b);               // 5
    k_last<<<NB, 256>>>(a, b);                                        // 6
    k_rowstats<<<NBLL, 256>>>(ma, mb, temp);                          // 7
    k_colstats<<<dim3(LL/32, NB), dim3(32,8)>>>(ma, mb, temp);        // 8
    k_ab<<<dim3(LL/64, DD/64, NB), 256>>>(b, ma, mb, temp, out_ia);   // 9
    k_ba<<<dim3(LL/64, DD/64, NB), 256>>>(a, ma, mb, temp, out_ib);   // 10
    k_metrics_a<<<NBLL, 256>>>(a, b, out_ma);                         // 11
    k_metrics_b<<<NBLL, 256>>>(a, b, out_mb);                         // 12
}

// round 15
// speedup vs baseline: 1.0717x; 1.0033x over previous
#include <cuda_runtime.h>
#include <cuda_bf16.h>
#include <float.h>
#include <math.h>

#define LL 512
#define DD 256
#define PP 20
#define NB 16
#define NBLL (NB*LL)
#define EPSF 1e-8f
#define NEGF -10000000.0f
#define MF4 (4*PP)

typedef unsigned long long u64;

__device__ __forceinline__ void ffma2(u64 &d, u64 a, u64 b) {
    asm("fma.rn.f32x2 %0, %1, %2, %0;" : "+l"(d) : "l"(a), "l"(b));
}
// warp-level bf16 tensor-core MMA (sm_80+, plain target)
__device__ __forceinline__ void mma16816(float* c, const unsigned* a, const unsigned* b) {
    asm volatile("mma.sync.aligned.m16n8k16.row.col.f32.bf16.bf16.f32 "
        "{%0,%1,%2,%3}, {%4,%5,%6,%7}, {%8,%9}, {%0,%1,%2,%3};"
        : "+f"(c[0]), "+f"(c[1]), "+f"(c[2]), "+f"(c[3])
        : "r"(a[0]), "r"(a[1]), "r"(a[2]), "r"(a[3]), "r"(b[0]), "r"(b[1]));
}

// ---------------- device scratch (allocation-free) ----------------
static __device__ float g_raw[NB*LL*LL];
static __device__ u64 g_amix[(size_t)PP*NBLL*128];   // (a*ws2_p): per k-pair (hi-pair u32, lo-pair u32)
static __device__ u64 g_bmix[(size_t)NBLL*128];      // b: per k-pair (hi-pair, lo-pair)
static __device__ float g_s2m[NB*LL*DD];
static __device__ float g_s1m[NB*LL*DD];
static __device__ float g_nra[NBLL];
static __device__ float g_nrb[NBLL];
static __device__ float g_rowmax[NBLL];
static __device__ float g_rowsuminv[NBLL];
static __device__ float g_arowsuminv[NBLL];
static __device__ float g_amax2[NBLL];
static __device__ float g_colmax[NBLL];
static __device__ float g_colsuminv[NBLL];
static __device__ float g_acolsuminv[NBLL];
static __device__ float g_amax1[NBLL];
static __device__ float g_na2[PP*NBLL];   // [p][bl]
static __device__ float g_nb2[PP*NBLL];   // [p][bl]
static __device__ float g_ws1[PP*DD];
static __device__ float g_ws2[PP*DD];
static __device__ float g_ws3[PP*DD];
static __device__ float g_ws4[PP*DD];
static __device__ float g_nbl[NB*PP];
static __device__ float g_nal[NB*PP];
static __device__ float g_wn[PP];

__device__ __forceinline__ void atomicMaxF(float* addr, float v) {
    int old = __float_as_int(*addr);
    while (__int_as_float(old) < v) {
        int prev = atomicCAS((int*)addr, old, __float_as_int(v));
        if (prev == old) break;
        old = prev;
    }
}

// ---------------- prep: squared weights + wn + mm_b init ----------------
__global__ void k_prep(const float* w1, const float* w2, const float* w3, const float* w4,
                       float* out_mb) {
    int p = blockIdx.x, d = threadIdx.x;
    float v1 = w1[p*DD+d]; g_ws1[p*DD+d] = v1*v1;
    float v2 = w2[p*DD+d]; g_ws2[p*DD+d] = v2*v2;
    float v3 = w3[p*DD+d]; g_ws3[p*DD+d] = v3*v3;
    float v4 = w4[p*DD+d]; float s4 = v4*v4; g_ws4[p*DD+d] = s4;
    __shared__ float red[256];
    red[d] = s4; __syncthreads();
    for (int o = 128; o; o >>= 1) { if (d < o) red[d] += red[d+o]; __syncthreads(); }
    if (d == 0) g_wn[p] = sqrtf(red[0]);
    for (int idx = blockIdx.x*256 + d; idx < NB*LL*PP; idx += PP*256) {
        int bl = idx / PP, pp = idx % PP;
        out_mb[bl*MF4 + PP + pp] = -FLT_MAX;
    }
}

// ---------------- splits: p<PP -> a*ws2_p ; p==PP -> b ; packed (hi-pair, lo-pair) u64 ----------------
__global__ void k_split(const float* A, const float* Bm) {
    int bl = blockIdx.x; int p = blockIdx.y; int d = threadIdx.x;
    float v;
    if (p < PP) v = A[bl*DD + d] * g_ws2[p*DD + d];
    else        v = Bm[bl*DD + d];
    __nv_bfloat16 h = __float2bfloat16(v);
    __nv_bfloat16 l = __float2bfloat16(v - __bfloat162float(h));
    unsigned hs = (unsigned)__bfloat16_as_ushort(h);
    unsigned ls = (unsigned)__bfloat16_as_ushort(l);
    unsigned hn = __shfl_down_sync(0xffffffffu, hs, 1);
    unsigned ln = __shfl_down_sync(0xffffffffu, ls, 1);
    if ((d & 1) == 0) {
        unsigned hp = hs | (hn << 16);   // low half = element k (little-endian)
        unsigned lp = ls | (ln << 16);
        u64 mix = (u64)hp | ((u64)lp << 32);
        if (p < PP) g_amix[((size_t)p*NBLL + bl)*128 + (d >> 1)] = mix;
        else        g_bmix[(size_t)bl*128 + (d >> 1)] = mix;
    }
}

// ---------------- plain L2 row norms ----------------
__global__ void k_rownorm(const float* A, const float* Bm) {
    int bl = blockIdx.x; int d = threadIdx.x;
    __shared__ float ra[256], rb[256];
    float av = A[bl*DD+d], bv = Bm[bl*DD+d];
    ra[d] = av*av; rb[d] = bv*bv; __syncthreads();
    for (int o = 128; o; o >>= 1) {
        if (d < o) { ra[d] += ra[d+o]; rb[d] += rb[d+o]; }
        __syncthreads();
    }
    if (d == 0) { g_nra[bl] = sqrtf(ra[0]); g_nrb[bl] = sqrtf(rb[0]); }
}

// ---------------- last-row weighted norms (w1^2) ----------------
__global__ void k_last(const float* A, const float* Bm) {
    int bb = blockIdx.x; int tid = threadIdx.x;
    int w = tid >> 5, lane = tid & 31;
    const float* al = A  + (bb*LL + LL-1)*DD;
    const float* bl_ = Bm + (bb*LL + LL-1)*DD;
    for (int p = w; p < PP; p += 8) {
        float sa = 0.f, sb = 0.f;
        for (int d = lane; d < DD; d += 32) {
            float wv = g_ws1[p*DD+d];
            float av = al[d], bv = bl_[d];
            sa += av*av*wv; sb += bv*bv*wv;
        }
        for (int o = 16; o; o >>= 1) {
            sa += __shfl_down_sync(0xffffffffu, sa, o);
            sb += __shfl_down_sync(0xffffffffu, sb, o);
        }
        if (lane == 0) { g_nal[bb*PP+p] = sqrtf(sa); g_nbl[bb*PP+p] = sqrtf(sb); }
    }
}

// ---------------- weighted norms for cos (w2^2), [p][bl] ----------------
__global__ void k_pnorm(const float* A, const float* Bm) {
    int bl = blockIdx.x; int side = blockIdx.y;
    const float* X = side ? Bm : A;
    float* out = side ? g_nb2 : g_na2;
    __shared__ float sx[DD];
    int tid = threadIdx.x;
    float v = X[bl*DD+tid]; sx[tid] = v*v;
    __syncthreads();
    int w = tid >> 5, lane = tid & 31;
    for (int p = w; p < PP; p += 8) {
        float s = 0.f;
        for (int d = lane; d < DD; d += 32) s += sx[d]*g_ws2[p*DD+d];
        for (int o = 16; o; o >>= 1) s += __shfl_down_sync(0xffffffffu, s, o);
        if (lane == 0) out[p*NBLL + bl] = sqrtf(s);
    }
}

// ---------------- cos tensor via mma.sync, packed hi/lo u64 (half the LDS) ----------------
__global__ __launch_bounds__(256) void k_cos_mma(float* out_ma, float* out_mb) {
    int bb = blockIdx.z, p = blockIdx.y, i0 = blockIdx.x*128;
    int tid = threadIdx.x, w = tid >> 5, lane = tid & 31;
    int g = lane >> 2, tg = lane & 3;
    __shared__ u64 Am[128*9];
    __shared__ u64 Bm2[64*9];
    __shared__ float nb_s[512];
    __shared__ float redc[8][64];
    nb_s[tid]       = g_nb2[p*NBLL + bb*LL + tid];
    nb_s[tid + 256] = g_nb2[p*NBLL + bb*LL + tid + 256];
    float na0 = g_na2[p*NBLL + bb*LL + i0 + w*16 + g];
    float na1 = g_na2[p*NBLL + bb*LL + i0 + w*16 + g + 8];
    const u64* gam = g_amix + ((size_t)p*NBLL + bb*LL + i0)*128;
    const u64* gbm = g_bmix + (size_t)(bb*LL)*128;
    float rmax0 = -FLT_MAX, rmax1 = -FLT_MAX;

    #pragma unroll 1
    for (int jt = 0; jt < 8; jt++) {
        int j0 = jt*64;
        float acc[8][4] = {};
        #pragma unroll 1
        for (int kc = 0; kc < 16; kc++) {
            int kp0 = kc*8;   // k-pair base
            #pragma unroll
            for (int e = 0; e < 4; e++) {
                int idx = tid + e*256; int r = idx >> 3, c2 = idx & 7;
                Am[r*9 + c2] = gam[(size_t)r*128 + kp0 + c2];
            }
            #pragma unroll
            for (int e = 0; e < 2; e++) {
                int idx = tid + e*256; int r = idx >> 3, c2 = idx & 7;
                Bm2[r*9 + c2] = gbm[(size_t)(j0 + r)*128 + kp0 + c2];
            }
            __syncthreads();
            u64 a0 = Am[(w*16 + g    )*9 + tg];
            u64 a1 = Am[(w*16 + g + 8)*9 + tg];
            u64 a2 = Am[(w*16 + g    )*9 + tg + 4];
            u64 a3 = Am[(w*16 + g + 8)*9 + tg + 4];
            unsigned ah[4], alr[4];
            ah[0]  = (unsigned)a0; alr[0] = (unsigned)(a0 >> 32);
            ah[1]  = (unsigned)a1; alr[1] = (unsigned)(a1 >> 32);
            ah[2]  = (unsigned)a2; alr[2] = (unsigned)(a2 >> 32);
            ah[3]  = (unsigned)a3; alr[3] = (unsigned)(a3 >> 32);
            #pragma unroll
            for (int nt = 0; nt < 8; nt++) {
                u64 b0 = Bm2[(nt*8 + g)*9 + tg];
                u64 b1 = Bm2[(nt*8 + g)*9 + tg + 4];
                unsigned bh[2], blr[2];
                bh[0]  = (unsigned)b0; blr[0] = (unsigned)(b0 >> 32);
                bh[1]  = (unsigned)b1; blr[1] = (unsigned)(b1 >> 32);
                mma16816(acc[nt], ah, bh);
                mma16816(acc[nt], ah, blr);
                mma16816(acc[nt], alr, bh);
            }
            __syncthreads();
        }
        // epilogue for this j-tile (R12-proven)
        #pragma unroll
        for (int nt = 0; nt < 8; nt++) {
            int c0 = j0 + nt*8 + tg*2, c1 = c0 + 1;
            float v00 = acc[nt][0] / (na0*nb_s[c0] + EPSF);
            float v01 = acc[nt][1] / (na0*nb_s[c1] + EPSF);
            float v10 = acc[nt][2] / (na1*nb_s[c0] + EPSF);
            float v11 = acc[nt][3] / (na1*nb_s[c1] + EPSF);
            rmax0 = fmaxf(rmax0, fmaxf(v00, v01));
            rmax1 = fmaxf(rmax1, fmaxf(v10, v11));
            float cm0 = fmaxf(v00, v10), cm1 = fmaxf(v01, v11);
            cm0 = fmaxf(cm0, __shfl_xor_sync(0xffffffffu, cm0, 4));
            cm1 = fmaxf(cm1, __shfl_xor_sync(0xffffffffu, cm1, 4));
            cm0 = fmaxf(cm0, __shfl_xor_sync(0xffffffffu, cm0, 8));
            cm1 = fmaxf(cm1, __shfl_xor_sync(0xffffffffu, cm1, 8));
            cm0 = fmaxf(cm0, __shfl_xor_sync(0xffffffffu, cm0, 16));
            cm1 = fmaxf(cm1, __shfl_xor_sync(0xffffffffu, cm1, 16));
            if (g == 0) {
                redc[w][nt*8 + tg*2]     = cm0;
                redc[w][nt*8 + tg*2 + 1] = cm1;
            }
        }
        __syncthreads();
        if (tid < 64) {
            float m = redc[0][tid];
            #pragma unroll
            for (int k = 1; k < 8; k++) m = fmaxf(m, redc[k][tid]);
            atomicMaxF(&out_mb[(bb*LL + j0 + tid)*MF4 + PP + p], m);
        }
        __syncthreads();
    }
    rmax0 = fmaxf(rmax0, __shfl_xor_sync(0xffffffffu, rmax0, 1));
    rmax1 = fmaxf(rmax1, __shfl_xor_sync(0xffffffffu, rmax1, 1));
    rmax0 = fmaxf(rmax0, __shfl_xor_sync(0xffffffffu, rmax0, 2));
    rmax1 = fmaxf(rmax1, __shfl_xor_sync(0xffffffffu, rmax1, 2));
    if (tg == 0) {
        out_ma[(bb*LL + i0 + w*16 + g    )*MF4 + PP + p] = rmax0;
        out_ma[(bb*LL + i0 + w*16 + g + 8)*MF4 + PP + p] = rmax1;
    }
}

// ---------------- raw = a @ b^T : FFMA2 A-dup + register-prefetch (R10-proven) ----------------
__global__ __launch_bounds__(256, 2) void k_gemm_raw(const float* A, const float* Bm) {
    int bb = blockIdx.z; int i0 = blockIdx.y*128; int j0 = blockIdx.x*64;
    int tid = threadIdx.x;
    int tx = tid & 15, ty = tid >> 4;
    __shared__ float Ad[2][16][260];
    __shared__ float Bs[16][68];
    const int c_ld = tid & 15;
    const int r_ld = tid >> 4;
    u64 acc[8][2] = {};
    float pa[8], pb[4];
    #pragma unroll
    for (int e = 0; e < 8; e++)
        pa[e] = A[(bb*LL + i0 + r_ld + e*16)*DD + c_ld];
    #pragma unroll
    for (int e = 0; e < 4; e++)
        pb[e] = Bm[(bb*LL + j0 + r_ld + e*16)*DD + c_ld];
    #pragma unroll
    for (int e = 0; e < 8; e++)
        *(float2*)&Ad[0][c_ld][2*(r_ld + e*16)] = make_float2(pa[e], pa[e]);
    #pragma unroll
    for (int e = 0; e < 4; e++)
        Bs[c_ld][r_ld + e*16] = pb[e];

    #pragma unroll 1
    for (int s = 0; s < 16; s++) {
        int buf = s & 1;
        __syncthreads();
        if (s + 1 < 16) {
            int k0n = (s + 1) * 16;
            #pragma unroll
            for (int e = 0; e < 8; e++)
                pa[e] = A[(bb*LL + i0 + r_ld + e*16)*DD + k0n + c_ld];
            #pragma unroll
            for (int e = 0; e < 4; e++)
                pb[e] = Bm[(bb*LL + j0 + r_ld + e*16)*DD + k0n + c_ld];
        }
        #pragma unroll
        for (int kk = 0; kk < 16; kk++) {
            u64 Ar[8], Br[2];
            ulonglong2 t;
            t = *(const ulonglong2*)&Ad[buf][kk][ty*16   ]; Ar[0]=t.x; Ar[1]=t.y;
            t = *(const ulonglong2*)&Ad[buf][kk][ty*16+ 4]; Ar[2]=t.x; Ar[3]=t.y;
            t = *(const ulonglong2*)&Ad[buf][kk][ty*16+ 8]; Ar[4]=t.x; Ar[5]=t.y;
            t = *(const ulonglong2*)&Ad[buf][kk][ty*16+12]; Ar[6]=t.x; Ar[7]=t.y;
            t = *(const ulonglong2*)&Bs[kk][tx*4]; Br[0]=t.x; Br[1]=t.y;
            #pragma unroll
            for (int r = 0; r < 8; r++) {
                ffma2(acc[r][0], Ar[r], Br[0]);
                ffma2(acc[r][1], Ar[r], Br[1]);
            }
        }
        __syncthreads();
        if (s + 1 < 16) {
            #pragma unroll
            for (int e = 0; e < 8; e++)
                *(float2*)&Ad[buf^1][c_ld][2*(r_ld + e*16)] = make_float2(pa[e], pa[e]);
            #pragma unroll
            for (int e = 0; e < 4; e++)
                Bs[c_ld][r_ld + e*16] = pb[e];
        }
    }
    #pragma unroll
    for (int r = 0; r < 8; r++) {
        ulonglong2 v; v.x = acc[r][0]; v.y = acc[r][1];
        *(ulonglong2*)&g_raw[(bb*LL + i0 + ty*8 + r)*LL + j0 + tx*4] = v;
    }
}

// ---------------- per-row stats ----------------
__global__ void k_rowstats(const int* ma, const int* mb, const float* temp_p) {
    int bl = blockIdx.x; int bb = bl / LL;
    int tid = threadIdx.x;
    __shared__ float s[LL];
    s[tid]       = g_raw[bl*LL + tid];
    s[tid + 256] = g_raw[bl*LL + tid + 256];
    __syncthreads();
    float temp = temp_p[0];
    int mai = ma[bl];
    float nrai = g_nra[bl];
    float mx = -FLT_MAX, amx = -FLT_MAX, asum = 0.f;
    for (int j = tid; j < LL; j += 256) {
        float rv = s[j];
        float attn = (mai && mb[bb*LL+j]) ? rv*temp : NEGF;
        mx = fmaxf(mx, attn);
        float al = rv / (nrai*g_nrb[bb*LL+j] + EPSF);
        amx = fmaxf(amx, al); asum += al;
    }
    __shared__ float red[256];
    red[tid] = mx; __syncthreads();
    for (int o = 128; o; o >>= 1) { if (tid < o) red[tid] = fmaxf(red[tid], red[tid+o]); __syncthreads(); }
    float MX = red[0]; __syncthreads();
    red[tid] = amx; __syncthreads();
    for (int o = 128; o; o >>= 1) { if (tid < o) red[tid] = fmaxf(red[tid], red[tid+o]); __syncthreads(); }
    float AMX = red[0]; __syncthreads();
    red[tid] = asum; __syncthreads();
    for (int o = 128; o; o >>= 1) { if (tid < o) red[tid] += red[tid+o]; __syncthreads(); }
    float ASUM = red[0]; __syncthreads();
    float se = 0.f;
    for (int j = tid; j < LL; j += 256) {
        float rv = s[j];
        float attn = (mai && mb[bb*LL+j]) ? rv*temp : NEGF;
        se += expf(attn - MX);
    }
    red[tid] = se; __syncthreads();
    for (int o = 128; o; o >>= 1) { if (tid < o) red[tid] += red[tid+o]; __syncthreads(); }
    if (tid == 0) {
        g_rowmax[bl] = MX;
        g_rowsuminv[bl] = 1.0f/red[0];
        g_arowsuminv[bl] = 1.0f/ASUM;
        g_amax2[bl] = AMX;
    }
}

// ---------------- per-col stats ----------------
__global__ void k_colstats(const int* ma, const int* mb, const float* temp_p) {
    int bb = blockIdx.y; int j = blockIdx.x*32 + threadIdx.x;
    int tx = threadIdx.x, ty = threadIdx.y;
    float temp = temp_p[0];
    int mbj = mb[bb*LL+j];
    float nrbj = g_nrb[bb*LL+j];
    float mx = -FLT_MAX, amx = -FLT_MAX, asum = 0.f;
    for (int i = ty; i < LL; i += 8) {
        float rv = g_raw[(bb*LL+i)*LL + j];
        float attn = (ma[bb*LL+i] && mbj) ? rv*temp : NEGF;
        mx = fmaxf(mx, attn);
        float al = rv / (g_nra[bb*LL+i]*nrbj + EPSF);
        amx = fmaxf(amx, al); asum += al;
    }
    __shared__ float r1[8][32], r2[8][32], r3[8][32];
    __shared__ float cm[32], cam[32], cas[32];
    r1[ty][tx] = mx; r2[ty][tx] = amx; r3[ty][tx] = asum;
    __syncthreads();
    if (ty == 0) {
        float m = r1[0][tx], a2 = r2[0][tx], s = r3[0][tx];
        for (int k = 1; k < 8; k++) { m = fmaxf(m, r1[k][tx]); a2 = fmaxf(a2, r2[k][tx]); s += r3[k][tx]; }
        cm[tx] = m; cam[tx] = a2; cas[tx] = s;
    }
    __syncthreads();
    float MX = cm[tx];
    float se = 0.f;
    for (int i = ty; i < LL; i += 8) {
        float rv = g_raw[(bb*LL+i)*LL + j];
        float attn = (ma[bb*LL+i] && mbj) ? rv*temp : NEGF;
        se += expf(attn - MX);
    }
    __syncthreads();
    r1[ty][tx] = se; __syncthreads();
    if (ty == 0) {
        float s = r1[0][tx];
        for (int k = 1; k < 8; k++) s += r1[k][tx];
        int idx = bb*LL+j;
        g_colmax[idx] = MX;
        g_colsuminv[idx] = 1.0f/s;
        g_acolsuminv[idx] = 1.0f/cas[tx];
        g_amax1[idx] = cam[tx];
    }
}

// ---------------- ia / s2_mean : FFMA2 dup-P/Q (proven) ----------------
__global__ __launch_bounds__(256) void k_ab(const float* Bm, const int* ma, const int* mb,
                                            const float* temp_p, float* out_ia) {
    int bb = blockIdx.z; int i0 = blockIdx.x*64; int d0 = blockIdx.y*64;
    int tid = threadIdx.x;
    int tx = tid & 15, ty = tid >> 4;
    float temp = temp_p[0];
    __shared__ float Pd[16][132], Qd[16][132], Bs[16][68];
    u64 accP[4][2] = {}, accQ[4][2] = {};
    for (int k0 = 0; k0 < LL; k0 += 16) {
        #pragma unroll
        for (int e = 0; e < 4; e++) {
            int idx = tid + e*256;
            int r = idx >> 4, c = idx & 15;
            int gi = bb*LL + i0 + r, gj = bb*LL + k0 + c;
            float rv = g_raw[gi*LL + k0 + c];
            float attn = (ma[gi] && mb[gj]) ? rv*temp : NEGF;
            float pv = expf(attn - g_rowmax[gi]) * g_rowsuminv[gi];
            float qv = rv / (g_nra[gi]*g_nrb[gj] + EPSF) * g_arowsuminv[gi];
            *(float2*)&Pd[c][2*r] = make_float2(pv, pv);
            *(float2*)&Qd[c][2*r] = make_float2(qv, qv);
        }
        #pragma unroll
        for (int e = 0; e < 4; e++) {
            int idx = tid + e*256; int r = idx >> 6, c = idx & 63;
            Bs[r][c] = Bm[(bb*LL + k0 + r)*DD + d0 + c];
        }
        __syncthreads();
        #pragma unroll
        for (int kk = 0; kk < 16; kk++) {
            u64 Pr[4], Qr[4], Br[2];
            ulonglong2 t;
            t = *(const ulonglong2*)&Pd[kk][ty*8   ]; Pr[0]=t.x; Pr[1]=t.y;
            t = *(const ulonglong2*)&Pd[kk][ty*8+ 4]; Pr[2]=t.x; Pr[3]=t.y;
            t = *(const ulonglong2*)&Qd[kk][ty*8   ]; Qr[0]=t.x; Qr[1]=t.y;
            t = *(const ulonglong2*)&Qd[kk][ty*8+ 4]; Qr[2]=t.x; Qr[3]=t.y;
            t = *(const ulonglong2*)&Bs[kk][tx*4]; Br[0]=t.x; Br[1]=t.y;
            #pragma unroll
            for (int r = 0; r < 4; r++) {
                ffma2(accP[r][0], Pr[r], Br[0]);
                ffma2(accP[r][1], Pr[r], Br[1]);
                ffma2(accQ[r][0], Qr[r], Br[0]);
                ffma2(accQ[r][1], Qr[r], Br[1]);
            }
        }
        __syncthreads();
    }
    #pragma unroll
    for (int r = 0; r < 4; r++) {
        int gi = bb*LL + i0 + ty*4 + r;
        ulonglong2 vp; vp.x = accP[r][0]; vp.y = accP[r][1];
        ulonglong2 vq; vq.x = accQ[r][0]; vq.y = accQ[r][1];
        *(ulonglong2*)&out_ia[gi*DD + d0 + tx*4] = vp;
        *(ulonglong2*)&g_s2m [gi*DD + d0 + tx*4] = vq;
    }
}

// ---------------- ib / s1_mean : FFMA2 dup-P/Q (proven) ----------------
__global__ __launch_bounds__(256) void k_ba(const float* A, const int* ma, const int* mb,
                                            const float* temp_p, float* out_ib) {
    int bb = blockIdx.z; int j0 = blockIdx.x*64; int d0 = blockIdx.y*64;
    int tid = threadIdx.x;
    int tx = tid & 15, ty = tid >> 4;
    float temp = temp_p[0];
    __shared__ float Pd[16][132], Qd[16][132], As[16][68];
    u64 accP[4][2] = {}, accQ[4][2] = {};
    for (int k0 = 0; k0 < LL; k0 += 16) {
        #pragma unroll
        for (int e = 0; e < 4; e++) {
            int idx = tid + e*256;
            int r = idx >> 6, c = idx & 63;
            int gi = bb*LL + k0 + r, gj = bb*LL + j0 + c;
            float rv = g_raw[gi*LL + j0 + c];
            float attn = (ma[gi] && mb[gj]) ? rv*temp : NEGF;
            float pv = expf(attn - g_colmax[gj]) * g_colsuminv[gj];
            float qv = rv / (g_nra[gi]*g_nrb[gj] + EPSF) * g_acolsuminv[gj];
            *(float2*)&Pd[r][2*c] = make_float2(pv, pv);
            *(float2*)&Qd[r][2*c] = make_float2(qv, qv);
            As[r][c] = A[(bb*LL + k0 + r)*DD + d0 + c];
        }
        __syncthreads();
        #pragma unroll
        for (int kk = 0; kk < 16; kk++) {
            u64 Pr[4], Qr[4], Br[2];
            ulonglong2 t;
            t = *(const ulonglong2*)&Pd[kk][ty*8   ]; Pr[0]=t.x; Pr[1]=t.y;
            t = *(const ulonglong2*)&Pd[kk][ty*8+ 4]; Pr[2]=t.x; Pr[3]=t.y;
            t = *(const ulonglong2*)&Qd[kk][ty*8   ]; Qr[0]=t.x; Qr[1]=t.y;
            t = *(const ulonglong2*)&Qd[kk][ty*8+ 4]; Qr[2]=t.x; Qr[3]=t.y;
            t = *(const ulonglong2*)&As[kk][tx*4]; Br[0]=t.x; Br[1]=t.y;
            #pragma unroll
            for (int r = 0; r < 4; r++) {
                ffma2(accP[r][0], Pr[r], Br[0]);
                ffma2(accP[r][1], Pr[r], Br[1]);
                ffma2(accQ[r][0], Qr[r], Br[0]);
                ffma2(accQ[r][1], Qr[r], Br[1]);
            }
        }
        __syncthreads();
    }
    #pragma unroll
    for (int r = 0; r < 4; r++) {
        int gj = bb*LL + j0 + ty*4 + r;
        ulonglong2 vp; vp.x = accP[r][0]; vp.y = accP[r][1];
        ulonglong2 vq; vq.x = accQ[r][0]; vq.y = accQ[r][1];
        *(ulonglong2*)&out_ib[gj*DD + d0 + tx*4] = vp;
        *(ulonglong2*)&g_s1m [gj*DD + d0 + tx*4] = vq;
    }
}

// ---------------- metrics a ----------------
__global__ void k_metrics_a(const float* A, const float* Bm, float* out_ma) {
    int bl = blockIdx.x; int bb = bl / LL;
    __shared__ float sa[DD], sm[DD], sl[DD];
    int tid = threadIdx.x;
    sa[tid] = A[bl*DD + tid];
    sm[tid] = g_s2m[bl*DD + tid];
    sl[tid] = Bm[(bb*LL + LL-1)*DD + tid];
    __syncthreads();
    float amax = g_amax2[bl];
    int w = tid >> 5, lane = tid & 31;
    for (int p = w; p < PP; p += 8) {
        float s_ab=0.f, s_a1=0.f, s_am=0.f, s_a3=0.f, s_m3=0.f, s_w4=0.f, s_a4=0.f;
        for (int d = lane; d < DD; d += 32) {
            float av = sa[d], mv = sm[d], lv = sl[d];
            float w1v = g_ws1[p*DD+d], w3v = g_ws3[p*DD+d], w4v = g_ws4[p*DD+d];
            s_ab += av*w1v*lv;  s_a1 += av*av*w1v;
            s_am += av*w3v*mv;  s_a3 += av*av*w3v;  s_m3 += mv*mv*w3v;
            s_w4 += av*w4v;     s_a4 += av*av*w4v;
        }
        for (int o = 16; o; o >>= 1) {
            s_ab += __shfl_down_sync(0xffffffffu, s_ab, o);
            s_a1 += __shfl_down_sync(0xffffffffu, s_a1, o);
            s_am += __shfl_down_sync(0xffffffffu, s_am, o);
            s_a3 += __shfl_down_sync(0xffffffffu, s_a3, o);
            s_m3 += __shfl_down_sync(0xffffffffu, s_m3, o);
            s_w4 += __shfl_down_sync(0xffffffffu, s_w4, o);
            s_a4 += __shfl_down_sync(0xffffffffu, s_a4, o);
        }
        if (lane == 0) {
            float* mrow = out_ma + bl*MF4;
            mrow[p]        = s_ab / fmaxf(sqrtf(s_a1)*g_nbl[bb*PP+p], EPSF);
            mrow[2*PP + p] = s_am / fmaxf(sqrtf(s_a3)*sqrtf(s_m3), EPSF);
            mrow[3*PP + p] = amax*s_w4 / fmaxf(sqrtf(s_a4)*fabsf(amax)*g_wn[p], EPSF);
        }
    }
}

// ---------------- metrics b ----------------
__global__ void k_metrics_b(const float* A, const float* Bm, float* out_mb) {
    int bl = blockIdx.x; int bb = bl / LL;
    __shared__ float sb[DD], sm[DD], sl[DD];
    int tid = threadIdx.x;
    sb[tid] = Bm[bl*DD + tid];
    sm[tid] = g_s1m[bl*DD + tid];
    sl[tid] = A[(bb*LL + LL-1)*DD + tid];
    __syncthreads();
    float amax = g_amax1[bl];
    int w = tid >> 5, lane = tid & 31;
    for (int p = w; p < PP; p += 8) {
        float s_ab=0.f, s_b1=0.f, s_am=0.f, s_b3=0.f, s_m3=0.f, s_w4=0.f, s_b4=0.f;
        for (int d = lane; d < DD; d += 32) {
            float bv = sb[d], mv = sm[d], lv = sl[d];
            float w1v = g_ws1[p*DD+d], w3v = g_ws3[p*DD+d], w4v = g_ws4[p*DD+d];
            s_ab += bv*w1v*lv;  s_b1 += bv*bv*w1v;
            s_am += bv*w3v*mv;  s_b3 += bv*bv*w3v;  s_m3 += mv*mv*w3v;
            s_w4 += bv*w4v;     s_b4 += bv*bv*w4v;
        }
        for (int o = 16; o; o >>= 1) {
            s_ab += __shfl_down_sync(0xffffffffu, s_ab, o);
            s_b1 += __shfl_down_sync(0xffffffffu, s_b1, o);
            s_am += __shfl_down_sync(0xffffffffu, s_am, o);
            s_b3 += __shfl_down_sync(0xffffffffu, s_b3, o);
            s_m3 += __shfl_down_sync(0xffffffffu, s_m3, o);
            s_w4 += __shfl_down_sync(0xffffffffu, s_w4, o);
            s_b4 += __shfl_down_sync(0xffffffffu, s_b4, o);
        }
        if (lane == 0) {
            float* mrow = out_mb + bl*MF4;
            mrow[p]        = s_ab / fmaxf(sqrtf(s_b1)*g_nal[bb*PP+p], EPSF);
            mrow[2*PP + p] = s_am / fmaxf(sqrtf(s_b3)*sqrtf(s_m3), EPSF);
            mrow[3*PP + p] = amax*s_w4 / fmaxf(sqrtf(s_b4)*fabsf(amax)*g_wn[p], EPSF);
        }
    }
}

// ---------------- launch (k_cos_mma at index 3 for the ncu window) ----------------
extern "C" void kernel_launch(void* const* d_in, const int* in_sizes, int n_in,
                              void* d_out, int out_size) {
    const float* a  = (const float*)d_in[0];
    const float* b  = (const float*)d_in[1];
    const int* ma   = (const int*)d_in[2];
    const int* mb   = (const int*)d_in[3];
    const float* w1 = (const float*)d_in[4];
    const float* w2 = (const float*)d_in[5];
    const float* w3 = (const float*)d_in[6];
    const float* w4 = (const float*)d_in[7];
    const float* temp = (const float*)d_in[8];

    float* out = (float*)d_out;
    float* out_ia = out;
    float* out_ib = out + NB*LL*DD;
    float* out_ma = out + 2*NB*LL*DD;
    float* out_mb = out_ma + NB*LL*MF4;

    k_prep<<<PP, 256>>>(w1, w2, w3, w4, out_mb);                      // 0
    k_split<<<dim3(NBLL, PP+1), 256>>>(a, b);                         // 1
    k_pnorm<<<dim3(NBLL, 2), 256>>>(a, b);                            // 2
    k_cos_mma<<<dim3(LL/128, PP, NB), 256>>>(out_ma, out_mb);         // 3 <- ncu window
    k_rownorm<<<NBLL, 256>>>(a, b);                                   // 4
    k_gemm_raw<<<dim3(LL/64, LL/128, NB), 256>>>(a, b);               // 5
    k_last<<<NB, 256>>>(a, b);                                        // 6
    k_rowstats<<<NBLL, 256>>>(ma, mb, temp);                          // 7
    k_colstats<<<dim3(LL/32, NB), dim3(32,8)>>>(ma, mb, temp);        // 8
    k_ab<<<dim3(LL/64, DD/64, NB), 256>>>(b, ma, mb, temp, out_ia);   // 9
    k_ba<<<dim3(LL/64, DD/64, NB), 256>>>(a, ma, mb, temp, out_ib);   // 10
    k_metrics_a<<<NBLL, 256>>>(a, b, out_ma);                         // 11
    k_metrics_b<<<NBLL, 256>>>(a, b, out_mb);                         // 12
}

// round 16
// speedup vs baseline: 1.1983x; 1.1182x over previous
#include <cuda_runtime.h>
#include <cuda_bf16.h>
#include <float.h>
#include <math.h>

#define LL 512
#define DD 256
#define PP 20
#define NB 16
#define NBLL (NB*LL)
#define EPSF 1e-8f
#define NEGF -10000000.0f
#define MF4 (4*PP)

typedef unsigned long long u64;

__device__ __forceinline__ void ffma2(u64 &d, u64 a, u64 b) {
    asm("fma.rn.f32x2 %0, %1, %2, %0;" : "+l"(d) : "l"(a), "l"(b));
}
// warp-level bf16 tensor-core MMA (sm_80+, plain target)
__device__ __forceinline__ void mma16816(float* c, const unsigned* a, const unsigned* b) {
    asm volatile("mma.sync.aligned.m16n8k16.row.col.f32.bf16.bf16.f32 "
        "{%0,%1,%2,%3}, {%4,%5,%6,%7}, {%8,%9}, {%0,%1,%2,%3};"
        : "+f"(c[0]), "+f"(c[1]), "+f"(c[2]), "+f"(c[3])
        : "r"(a[0]), "r"(a[1]), "r"(a[2]), "r"(a[3]), "r"(b[0]), "r"(b[1]));
}

// ---------------- device scratch (allocation-free) ----------------
static __device__ float g_raw[NB*LL*LL];
static __device__ u64 g_amix[(size_t)PP*NBLL*128];   // (a*ws2_p): per k-pair (hi-pair u32, lo-pair u32)
static __device__ u64 g_bmix[(size_t)NBLL*128];      // b: per k-pair (hi-pair, lo-pair)
static __device__ float g_s2m[NB*LL*DD];
static __device__ float g_s1m[NB*LL*DD];
static __device__ float g_nra[NBLL];
static __device__ float g_nrb[NBLL];
static __device__ float g_rowmax[NBLL];
static __device__ float g_rowsuminv[NBLL];
static __device__ float g_arowsuminv[NBLL];
static __device__ float g_amax2[NBLL];
static __device__ float g_colmax[NBLL];
static __device__ float g_colsuminv[NBLL];
static __device__ float g_acolsuminv[NBLL];
static __device__ float g_amax1[NBLL];
static __device__ float g_na2[PP*NBLL];   // [p][bl]
static __device__ float g_nb2[PP*NBLL];   // [p][bl]
static __device__ float g_ws1[PP*DD];
static __device__ float g_ws2[PP*DD];
static __device__ float g_ws3[PP*DD];
static __device__ float g_ws4[PP*DD];
static __device__ float g_nbl[NB*PP];
static __device__ float g_nal[NB*PP];
static __device__ float g_wn[PP];

__device__ __forceinline__ void atomicMaxF(float* addr, float v) {
    int old = __float_as_int(*addr);
    while (__int_as_float(old) < v) {
        int prev = atomicCAS((int*)addr, old, __float_as_int(v));
        if (prev == old) break;
        old = prev;
    }
}

// ---------------- prep: squared weights + wn + mm_b init ----------------
__global__ void k_prep(const float* w1, const float* w2, const float* w3, const float* w4,
                       float* out_mb) {
    int p = blockIdx.x, d = threadIdx.x;
    float v1 = w1[p*DD+d]; g_ws1[p*DD+d] = v1*v1;
    float v2 = w2[p*DD+d]; g_ws2[p*DD+d] = v2*v2;
    float v3 = w3[p*DD+d]; g_ws3[p*DD+d] = v3*v3;
    float v4 = w4[p*DD+d]; float s4 = v4*v4; g_ws4[p*DD+d] = s4;
    __shared__ float red[256];
    red[d] = s4; __syncthreads();
    for (int o = 128; o; o >>= 1) { if (d < o) red[d] += red[d+o]; __syncthreads(); }
    if (d == 0) g_wn[p] = sqrtf(red[0]);
    for (int idx = blockIdx.x*256 + d; idx < NB*LL*PP; idx += PP*256) {
        int bl = idx / PP, pp = idx % PP;
        out_mb[bl*MF4 + PP + pp] = -FLT_MAX;
    }
}

// ---------------- splits: p<PP -> a*ws2_p ; p==PP -> b ; packed (hi-pair, lo-pair) u64 ----------------
__global__ void k_split(const float* A, const float* Bm) {
    int bl = blockIdx.x; int p = blockIdx.y; int d = threadIdx.x;
    float v;
    if (p < PP) v = A[bl*DD + d] * g_ws2[p*DD + d];
    else        v = Bm[bl*DD + d];
    __nv_bfloat16 h = __float2bfloat16(v);
    __nv_bfloat16 l = __float2bfloat16(v - __bfloat162float(h));
    unsigned hs = (unsigned)__bfloat16_as_ushort(h);
    unsigned ls = (unsigned)__bfloat16_as_ushort(l);
    unsigned hn = __shfl_down_sync(0xffffffffu, hs, 1);
    unsigned ln = __shfl_down_sync(0xffffffffu, ls, 1);
    if ((d & 1) == 0) {
        unsigned hp = hs | (hn << 16);   // low half = element k (little-endian)
        unsigned lp = ls | (ln << 16);
        u64 mix = (u64)hp | ((u64)lp << 32);
        if (p < PP) g_amix[((size_t)p*NBLL + bl)*128 + (d >> 1)] = mix;
        else        g_bmix[(size_t)bl*128 + (d >> 1)] = mix;
    }
}

// ---------------- plain L2 row norms ----------------
__global__ void k_rownorm(const float* A, const float* Bm) {
    int bl = blockIdx.x; int d = threadIdx.x;
    __shared__ float ra[256], rb[256];
    float av = A[bl*DD+d], bv = Bm[bl*DD+d];
    ra[d] = av*av; rb[d] = bv*bv; __syncthreads();
    for (int o = 128; o; o >>= 1) {
        if (d < o) { ra[d] += ra[d+o]; rb[d] += rb[d+o]; }
        __syncthreads();
    }
    if (d == 0) { g_nra[bl] = sqrtf(ra[0]); g_nrb[bl] = sqrtf(rb[0]); }
}

// ---------------- last-row weighted norms (w1^2) ----------------
__global__ void k_last(const float* A, const float* Bm) {
    int bb = blockIdx.x; int tid = threadIdx.x;
    int w = tid >> 5, lane = tid & 31;
    const float* al = A  + (bb*LL + LL-1)*DD;
    const float* bl_ = Bm + (bb*LL + LL-1)*DD;
    for (int p = w; p < PP; p += 8) {
        float sa = 0.f, sb = 0.f;
        for (int d = lane; d < DD; d += 32) {
            float wv = g_ws1[p*DD+d];
            float av = al[d], bv = bl_[d];
            sa += av*av*wv; sb += bv*bv*wv;
        }
        for (int o = 16; o; o >>= 1) {
            sa += __shfl_down_sync(0xffffffffu, sa, o);
            sb += __shfl_down_sync(0xffffffffu, sb, o);
        }
        if (lane == 0) { g_nal[bb*PP+p] = sqrtf(sa); g_nbl[bb*PP+p] = sqrtf(sb); }
    }
}

// ---------------- weighted norms for cos (w2^2), [p][bl] ----------------
__global__ void k_pnorm(const float* A, const float* Bm) {
    int bl = blockIdx.x; int side = blockIdx.y;
    const float* X = side ? Bm : A;
    float* out = side ? g_nb2 : g_na2;
    __shared__ float sx[DD];
    int tid = threadIdx.x;
    float v = X[bl*DD+tid]; sx[tid] = v*v;
    __syncthreads();
    int w = tid >> 5, lane = tid & 31;
    for (int p = w; p < PP; p += 8) {
        float s = 0.f;
        for (int d = lane; d < DD; d += 32) s += sx[d]*g_ws2[p*DD+d];
        for (int o = 16; o; o >>= 1) s += __shfl_down_sync(0xffffffffu, s, o);
        if (lane == 0) out[p*NBLL + bl] = sqrtf(s);
    }
}

// ---------------- cos tensor via mma.sync, packed u64, double-buffered pipeline ----------------
__global__ __launch_bounds__(256) void k_cos_mma(float* out_ma, float* out_mb) {
    int bb = blockIdx.z, p = blockIdx.y, i0 = blockIdx.x*128;
    int tid = threadIdx.x, w = tid >> 5, lane = tid & 31;
    int g = lane >> 2, tg = lane & 3;
    __shared__ u64 Am[2][128*9];
    __shared__ u64 Bm2[2][64*9];
    __shared__ float nb_s[512];
    __shared__ float redc[8][64];
    nb_s[tid]       = g_nb2[p*NBLL + bb*LL + tid];
    nb_s[tid + 256] = g_nb2[p*NBLL + bb*LL + tid + 256];
    float na0 = g_na2[p*NBLL + bb*LL + i0 + w*16 + g];
    float na1 = g_na2[p*NBLL + bb*LL + i0 + w*16 + g + 8];
    const u64* gam = g_amix + ((size_t)p*NBLL + bb*LL + i0)*128;
    const u64* gbm = g_bmix + (size_t)(bb*LL)*128;
    float rmax0 = -FLT_MAX, rmax1 = -FLT_MAX;
    // staging index decomposition (same for A and B)
    const int r_a = tid >> 3, c_a = tid & 7;     // A: 4 chunks of 32 rows
    float acc[8][4] = {};

    // prologue: stage t=0 (jt=0, kc=0) into buf 0
    #pragma unroll
    for (int e = 0; e < 4; e++)
        Am[0][(r_a + e*32)*9 + c_a] = gam[(size_t)(r_a + e*32)*128 + c_a];
    #pragma unroll
    for (int e = 0; e < 2; e++)
        Bm2[0][(r_a + e*32)*9 + c_a] = gbm[(size_t)(r_a + e*32)*128 + c_a];
    __syncthreads();

    #pragma unroll 1
    for (int t = 0; t < 128; t++) {
        int buf = t & 1;
        // prefetch t+1 into registers (LDG latency hidden under mma)
        u64 ra[4], rb[2];
        if (t + 1 < 128) {
            int kp0n = ((t + 1) & 15) * 8;
            int j0n = ((t + 1) >> 4) * 64;
            #pragma unroll
            for (int e = 0; e < 4; e++)
                ra[e] = gam[(size_t)(r_a + e*32)*128 + kp0n + c_a];
            #pragma unroll
            for (int e = 0; e < 2; e++)
                rb[e] = gbm[(size_t)(j0n + r_a + e*32)*128 + kp0n + c_a];
        }
        // compute step t from buf
        u64 a0 = Am[buf][(w*16 + g    )*9 + tg];
        u64 a1 = Am[buf][(w*16 + g + 8)*9 + tg];
        u64 a2 = Am[buf][(w*16 + g    )*9 + tg + 4];
        u64 a3 = Am[buf][(w*16 + g + 8)*9 + tg + 4];
        unsigned ah[4], alr[4];
        ah[0]  = (unsigned)a0; alr[0] = (unsigned)(a0 >> 32);
        ah[1]  = (unsigned)a1; alr[1] = (unsigned)(a1 >> 32);
        ah[2]  = (unsigned)a2; alr[2] = (unsigned)(a2 >> 32);
        ah[3]  = (unsigned)a3; alr[3] = (unsigned)(a3 >> 32);
        #pragma unroll
        for (int nt = 0; nt < 8; nt++) {
            u64 b0 = Bm2[buf][(nt*8 + g)*9 + tg];
            u64 b1 = Bm2[buf][(nt*8 + g)*9 + tg + 4];
            unsigned bh[2], blr[2];
            bh[0]  = (unsigned)b0; blr[0] = (unsigned)(b0 >> 32);
            bh[1]  = (unsigned)b1; blr[1] = (unsigned)(b1 >> 32);
            mma16816(acc[nt], ah, bh);
            mma16816(acc[nt], ah, blr);
            mma16816(acc[nt], alr, bh);
        }
        // store t+1 into the other buffer (readers of it finished at end of t-1)
        if (t + 1 < 128) {
            #pragma unroll
            for (int e = 0; e < 4; e++)
                Am[buf^1][(r_a + e*32)*9 + c_a] = ra[e];
            #pragma unroll
            for (int e = 0; e < 2; e++)
                Bm2[buf^1][(r_a + e*32)*9 + c_a] = rb[e];
        }
        // epilogue at end of each j-tile (R12-proven math)
        if ((t & 15) == 15) {
            int j0 = (t >> 4) * 64;
            #pragma unroll
            for (int nt = 0; nt < 8; nt++) {
                int c0 = j0 + nt*8 + tg*2, c1 = c0 + 1;
                float v00 = acc[nt][0] / (na0*nb_s[c0] + EPSF);
                float v01 = acc[nt][1] / (na0*nb_s[c1] + EPSF);
                float v10 = acc[nt][2] / (na1*nb_s[c0] + EPSF);
                float v11 = acc[nt][3] / (na1*nb_s[c1] + EPSF);
                rmax0 = fmaxf(rmax0, fmaxf(v00, v01));
                rmax1 = fmaxf(rmax1, fmaxf(v10, v11));
                float cm0 = fmaxf(v00, v10), cm1 = fmaxf(v01, v11);
                cm0 = fmaxf(cm0, __shfl_xor_sync(0xffffffffu, cm0, 4));
                cm1 = fmaxf(cm1, __shfl_xor_sync(0xffffffffu, cm1, 4));
                cm0 = fmaxf(cm0, __shfl_xor_sync(0xffffffffu, cm0, 8));
                cm1 = fmaxf(cm1, __shfl_xor_sync(0xffffffffu, cm1, 8));
                cm0 = fmaxf(cm0, __shfl_xor_sync(0xffffffffu, cm0, 16));
                cm1 = fmaxf(cm1, __shfl_xor_sync(0xffffffffu, cm1, 16));
                if (g == 0) {
                    redc[w][nt*8 + tg*2]     = cm0;
                    redc[w][nt*8 + tg*2 + 1] = cm1;
                }
                acc[nt][0] = 0.f; acc[nt][1] = 0.f; acc[nt][2] = 0.f; acc[nt][3] = 0.f;
            }
            __syncthreads();
            if (tid < 64) {
                float m = redc[0][tid];
                #pragma unroll
                for (int k = 1; k < 8; k++) m = fmaxf(m, redc[k][tid]);
                atomicMaxF(&out_mb[(bb*LL + j0 + tid)*MF4 + PP + p], m);
            }
        }
        __syncthreads();   // all reads of buf done; buf^1 writes visible for step t+1
    }
    rmax0 = fmaxf(rmax0, __shfl_xor_sync(0xffffffffu, rmax0, 1));
    rmax1 = fmaxf(rmax1, __shfl_xor_sync(0xffffffffu, rmax1, 1));
    rmax0 = fmaxf(rmax0, __shfl_xor_sync(0xffffffffu, rmax0, 2));
    rmax1 = fmaxf(rmax1, __shfl_xor_sync(0xffffffffu, rmax1, 2));
    if (tg == 0) {
        out_ma[(bb*LL + i0 + w*16 + g    )*MF4 + PP + p] = rmax0;
        out_ma[(bb*LL + i0 + w*16 + g + 8)*MF4 + PP + p] = rmax1;
    }
}

// ---------------- raw = a @ b^T : FFMA2 A-dup + register-prefetch (R10-proven) ----------------
__global__ __launch_bounds__(256, 2) void k_gemm_raw(const float* A, const float* Bm) {
    int bb = blockIdx.z; int i0 = blockIdx.y*128; int j0 = blockIdx.x*64;
    int tid = threadIdx.x;
    int tx = tid & 15, ty = tid >> 4;
    __shared__ float Ad[2][16][260];
    __shared__ float Bs[16][68];
    const int c_ld = tid & 15;
    const int r_ld = tid >> 4;
    u64 acc[8][2] = {};
    float pa[8], pb[4];
    #pragma unroll
    for (int e = 0; e < 8; e++)
        pa[e] = A[(bb*LL + i0 + r_ld + e*16)*DD + c_ld];
    #pragma unroll
    for (int e = 0; e < 4; e++)
        pb[e] = Bm[(bb*LL + j0 + r_ld + e*16)*DD + c_ld];
    #pragma unroll
    for (int e = 0; e < 8; e++)
        *(float2*)&Ad[0][c_ld][2*(r_ld + e*16)] = make_float2(pa[e], pa[e]);
    #pragma unroll
    for (int e = 0; e < 4; e++)
        Bs[c_ld][r_ld + e*16] = pb[e];

    #pragma unroll 1
    for (int s = 0; s < 16; s++) {
        int buf = s & 1;
        __syncthreads();
        if (s + 1 < 16) {
            int k0n = (s + 1) * 16;
            #pragma unroll
            for (int e = 0; e < 8; e++)
                pa[e] = A[(bb*LL + i0 + r_ld + e*16)*DD + k0n + c_ld];
            #pragma unroll
            for (int e = 0; e < 4; e++)
                pb[e] = Bm[(bb*LL + j0 + r_ld + e*16)*DD + k0n + c_ld];
        }
        #pragma unroll
        for (int kk = 0; kk < 16; kk++) {
            u64 Ar[8], Br[2];
            ulonglong2 t;
            t = *(const ulonglong2*)&Ad[buf][kk][ty*16   ]; Ar[0]=t.x; Ar[1]=t.y;
            t = *(const ulonglong2*)&Ad[buf][kk][ty*16+ 4]; Ar[2]=t.x; Ar[3]=t.y;
            t = *(const ulonglong2*)&Ad[buf][kk][ty*16+ 8]; Ar[4]=t.x; Ar[5]=t.y;
            t = *(const ulonglong2*)&Ad[buf][kk][ty*16+12]; Ar[6]=t.x; Ar[7]=t.y;
            t = *(const ulonglong2*)&Bs[kk][tx*4]; Br[0]=t.x; Br[1]=t.y;
            #pragma unroll
            for (int r = 0; r < 8; r++) {
                ffma2(acc[r][0], Ar[r], Br[0]);
                ffma2(acc[r][1], Ar[r], Br[1]);
            }
        }
        __syncthreads();
        if (s + 1 < 16) {
            #pragma unroll
            for (int e = 0; e < 8; e++)
                *(float2*)&Ad[buf^1][c_ld][2*(r_ld + e*16)] = make_float2(pa[e], pa[e]);
            #pragma unroll
            for (int e = 0; e < 4; e++)
                Bs[c_ld][r_ld + e*16] = pb[e];
        }
    }
    #pragma unroll
    for (int r = 0; r < 8; r++) {
        ulonglong2 v; v.x = acc[r][0]; v.y = acc[r][1];
        *(ulonglong2*)&g_raw[(bb*LL + i0 + ty*8 + r)*LL + j0 + tx*4] = v;
    }
}

// ---------------- per-row stats ----------------
__global__ void k_rowstats(const int* ma, const int* mb, const float* temp_p) {
    int bl = blockIdx.x; int bb = bl / LL;
    int tid = threadIdx.x;
    __shared__ float s[LL];
    s[tid]       = g_raw[bl*LL + tid];
    s[tid + 256] = g_raw[bl*LL + tid + 256];
    __syncthreads();
    float temp = temp_p[0];
    int mai = ma[bl];
    float nrai = g_nra[bl];
    float mx = -FLT_MAX, amx = -FLT_MAX, asum = 0.f;
    for (int j = tid; j < LL; j += 256) {
        float rv = s[j];
        float attn = (mai && mb[bb*LL+j]) ? rv*temp : NEGF;
        mx = fmaxf(mx, attn);
        float al = rv / (nrai*g_nrb[bb*LL+j] + EPSF);
        amx = fmaxf(amx, al); asum += al;
    }
    __shared__ float red[256];
    red[tid] = mx; __syncthreads();
    for (int o = 128; o; o >>= 1) { if (tid < o) red[tid] = fmaxf(red[tid], red[tid+o]); __syncthreads(); }
    float MX = red[0]; __syncthreads();
    red[tid] = amx; __syncthreads();
    for (int o = 128; o; o >>= 1) { if (tid < o) red[tid] = fmaxf(red[tid], red[tid+o]); __syncthreads(); }
    float AMX = red[0]; __syncthreads();
    red[tid] = asum; __syncthreads();
    for (int o = 128; o; o >>= 1) { if (tid < o) red[tid] += red[tid+o]; __syncthreads(); }
    float ASUM = red[0]; __syncthreads();
    float se = 0.f;
    for (int j = tid; j < LL; j += 256) {
        float rv = s[j];
        float attn = (mai && mb[bb*LL+j]) ? rv*temp : NEGF;
        se += expf(attn - MX);
    }
    red[tid] = se; __syncthreads();
    for (int o = 128; o; o >>= 1) { if (tid < o) red[tid] += red[tid+o]; __syncthreads(); }
    if (tid == 0) {
        g_rowmax[bl] = MX;
        g_rowsuminv[bl] = 1.0f/red[0];
        g_arowsuminv[bl] = 1.0f/ASUM;
        g_amax2[bl] = AMX;
    }
}

// ---------------- per-col stats ----------------
__global__ void k_colstats(const int* ma, const int* mb, const float* temp_p) {
    int bb = blockIdx.y; int j = blockIdx.x*32 + threadIdx.x;
    int tx = threadIdx.x, ty = threadIdx.y;
    float temp = temp_p[0];
    int mbj = mb[bb*LL+j];
    float nrbj = g_nrb[bb*LL+j];
    float mx = -FLT_MAX, amx = -FLT_MAX, asum = 0.f;
    for (int i = ty; i < LL; i += 8) {
        float rv = g_raw[(bb*LL+i)*LL + j];
        float attn = (ma[bb*LL+i] && mbj) ? rv*temp : NEGF;
        mx = fmaxf(mx, attn);
        float al = rv / (g_nra[bb*LL+i]*nrbj + EPSF);
        amx = fmaxf(amx, al); asum += al;
    }
    __shared__ float r1[8][32], r2[8][32], r3[8][32];
    __shared__ float cm[32], cam[32], cas[32];
    r1[ty][tx] = mx; r2[ty][tx] = amx; r3[ty][tx] = asum;
    __syncthreads();
    if (ty == 0) {
        float m = r1[0][tx], a2 = r2[0][tx], s = r3[0][tx];
        for (int k = 1; k < 8; k++) { m = fmaxf(m, r1[k][tx]); a2 = fmaxf(a2, r2[k][tx]); s += r3[k][tx]; }
        cm[tx] = m; cam[tx] = a2; cas[tx] = s;
    }
    __syncthreads();
    float MX = cm[tx];
    float se = 0.f;
    for (int i = ty; i < LL; i += 8) {
        float rv = g_raw[(bb*LL+i)*LL + j];
        float attn = (ma[bb*LL+i] && mbj) ? rv*temp : NEGF;
        se += expf(attn - MX);
    }
    __syncthreads();
    r1[ty][tx] = se; __syncthreads();
    if (ty == 0) {
        float s = r1[0][tx];
        for (int k = 1; k < 8; k++) s += r1[k][tx];
        int idx = bb*LL+j;
        g_colmax[idx] = MX;
        g_colsuminv[idx] = 1.0f/s;
        g_acolsuminv[idx] = 1.0f/cas[tx];
        g_amax1[idx] = cam[tx];
    }
}

// ---------------- ia / s2_mean : FFMA2 dup-P/Q (proven) ----------------
__global__ __launch_bounds__(256) void k_ab(const float* Bm, const int* ma, const int* mb,
                                            const float* temp_p, float* out_ia) {
    int bb = blockIdx.z; int i0 = blockIdx.x*64; int d0 = blockIdx.y*64;
    int tid = threadIdx.x;
    int tx = tid & 15, ty = tid >> 4;
    float temp = temp_p[0];
    __shared__ float Pd[16][132], Qd[16][132], Bs[16][68];
    u64 accP[4][2] = {}, accQ[4][2] = {};
    for (int k0 = 0; k0 < LL; k0 += 16) {
        #pragma unroll
        for (int e = 0; e < 4; e++) {
            int idx = tid + e*256;
            int r = idx >> 4, c = idx & 15;
            int gi = bb*LL + i0 + r, gj = bb*LL + k0 + c;
            float rv = g_raw[gi*LL + k0 + c];
            float attn = (ma[gi] && mb[gj]) ? rv*temp : NEGF;
            float pv = expf(attn - g_rowmax[gi]) * g_rowsuminv[gi];
            float qv = rv / (g_nra[gi]*g_nrb[gj] + EPSF) * g_arowsuminv[gi];
            *(float2*)&Pd[c][2*r] = make_float2(pv, pv);
            *(float2*)&Qd[c][2*r] = make_float2(qv, qv);
        }
        #pragma unroll
        for (int e = 0; e < 4; e++) {
            int idx = tid + e*256; int r = idx >> 6, c = idx & 63;
            Bs[r][c] = Bm[(bb*LL + k0 + r)*DD + d0 + c];
        }
        __syncthreads();
        #pragma unroll
        for (int kk = 0; kk < 16; kk++) {
            u64 Pr[4], Qr[4], Br[2];
            ulonglong2 t;
            t = *(const ulonglong2*)&Pd[kk][ty*8   ]; Pr[0]=t.x; Pr[1]=t.y;
            t = *(const ulonglong2*)&Pd[kk][ty*8+ 4]; Pr[2]=t.x; Pr[3]=t.y;
            t = *(const ulonglong2*)&Qd[kk][ty*8   ]; Qr[0]=t.x; Qr[1]=t.y;
            t = *(const ulonglong2*)&Qd[kk][ty*8+ 4]; Qr[2]=t.x; Qr[3]=t.y;
            t = *(const ulonglong2*)&Bs[kk][tx*4]; Br[0]=t.x; Br[1]=t.y;
            #pragma unroll
            for (int r = 0; r < 4; r++) {
                ffma2(accP[r][0], Pr[r], Br[0]);
                ffma2(accP[r][1], Pr[r], Br[1]);
                ffma2(accQ[r][0], Qr[r], Br[0]);
                ffma2(accQ[r][1], Qr[r], Br[1]);
            }
        }
        __syncthreads();
    }
    #pragma unroll
    for (int r = 0; r < 4; r++) {
        int gi = bb*LL + i0 + ty*4 + r;
        ulonglong2 vp; vp.x = accP[r][0]; vp.y = accP[r][1];
        ulonglong2 vq; vq.x = accQ[r][0]; vq.y = accQ[r][1];
        *(ulonglong2*)&out_ia[gi*DD + d0 + tx*4] = vp;
        *(ulonglong2*)&g_s2m [gi*DD + d0 + tx*4] = vq;
    }
}

// ---------------- ib / s1_mean : FFMA2 dup-P/Q (proven) ----------------
__global__ __launch_bounds__(256) void k_ba(const float* A, const int* ma, const int* mb,
                                            const float* temp_p, float* out_ib) {
    int bb = blockIdx.z; int j0 = blockIdx.x*64; int d0 = blockIdx.y*64;
    int tid = threadIdx.x;
    int tx = tid & 15, ty = tid >> 4;
    float temp = temp_p[0];
    __shared__ float Pd[16][132], Qd[16][132], As[16][68];
    u64 accP[4][2] = {}, accQ[4][2] = {};
    for (int k0 = 0; k0 < LL; k0 += 16) {
        #pragma unroll
        for (int e = 0; e < 4; e++) {
            int idx = tid + e*256;
            int r = idx >> 6, c = idx & 63;
            int gi = bb*LL + k0 + r, gj = bb*LL + j0 + c;
            float rv = g_raw[gi*LL + j0 + c];
            float attn = (ma[gi] && mb[gj]) ? rv*temp : NEGF;
            float pv = expf(attn - g_colmax[gj]) * g_colsuminv[gj];
            float qv = rv / (g_nra[gi]*g_nrb[gj] + EPSF) * g_acolsuminv[gj];
            *(float2*)&Pd[r][2*c] = make_float2(pv, pv);
            *(float2*)&Qd[r][2*c] = make_float2(qv, qv);
            As[r][c] = A[(bb*LL + k0 + r)*DD + d0 + c];
        }
        __syncthreads();
        #pragma unroll
        for (int kk = 0; kk < 16; kk++) {
            u64 Pr[4], Qr[4], Br[2];
            ulonglong2 t;
            t = *(const ulonglong2*)&Pd[kk][ty*8   ]; Pr[0]=t.x; Pr[1]=t.y;
            t = *(const ulonglong2*)&Pd[kk][ty*8+ 4]; Pr[2]=t.x; Pr[3]=t.y;
            t = *(const ulonglong2*)&Qd[kk][ty*8   ]; Qr[0]=t.x; Qr[1]=t.y;
            t = *(const ulonglong2*)&Qd[kk][ty*8+ 4]; Qr[2]=t.x; Qr[3]=t.y;
            t = *(const ulonglong2*)&As[kk][tx*4]; Br[0]=t.x; Br[1]=t.y;
            #pragma unroll
            for (int r = 0; r < 4; r++) {
                ffma2(accP[r][0], Pr[r], Br[0]);
                ffma2(accP[r][1], Pr[r], Br[1]);
                ffma2(accQ[r][0], Qr[r], Br[0]);
                ffma2(accQ[r][1], Qr[r], Br[1]);
            }
        }
        __syncthreads();
    }
    #pragma unroll
    for (int r = 0; r < 4; r++) {
        int gj = bb*LL + j0 + ty*4 + r;
        ulonglong2 vp; vp.x = accP[r][0]; vp.y = accP[r][1];
        ulonglong2 vq; vq.x = accQ[r][0]; vq.y = accQ[r][1];
        *(ulonglong2*)&out_ib[gj*DD + d0 + tx*4] = vp;
        *(ulonglong2*)&g_s1m [gj*DD + d0 + tx*4] = vq;
    }
}

// ---------------- metrics a ----------------
__global__ void k_metrics_a(const float* A, const float* Bm, float* out_ma) {
    int bl = blockIdx.x; int bb = bl / LL;
    __shared__ float sa[DD], sm[DD], sl[DD];
    int tid = threadIdx.x;
    sa[tid] = A[bl*DD + tid];
    sm[tid] = g_s2m[bl*DD + tid];
    sl[tid] = Bm[(bb*LL + LL-1)*DD + tid];
    __syncthreads();
    float amax = g_amax2[bl];
    int w = tid >> 5, lane = tid & 31;
    for (int p = w; p < PP; p += 8) {
        float s_ab=0.f, s_a1=0.f, s_am=0.f, s_a3=0.f, s_m3=0.f, s_w4=0.f, s_a4=0.f;
        for (int d = lane; d < DD; d += 32) {
            float av = sa[d], mv = sm[d], lv = sl[d];
            float w1v = g_ws1[p*DD+d], w3v = g_ws3[p*DD+d], w4v = g_ws4[p*DD+d];
            s_ab += av*w1v*lv;  s_a1 += av*av*w1v;
            s_am += av*w3v*mv;  s_a3 += av*av*w3v;  s_m3 += mv*mv*w3v;
            s_w4 += av*w4v;     s_a4 += av*av*w4v;
        }
        for (int o = 16; o; o >>= 1) {
            s_ab += __shfl_down_sync(0xffffffffu, s_ab, o);
            s_a1 += __shfl_down_sync(0xffffffffu, s_a1, o);
            s_am += __shfl_down_sync(0xffffffffu, s_am, o);
            s_a3 += __shfl_down_sync(0xffffffffu, s_a3, o);
            s_m3 += __shfl_down_sync(0xffffffffu, s_m3, o);
            s_w4 += __shfl_down_sync(0xffffffffu, s_w4, o);
            s_a4 += __shfl_down_sync(0xffffffffu, s_a4, o);
        }
        if (lane == 0) {
            float* mrow = out_ma + bl*MF4;
            mrow[p]        = s_ab / fmaxf(sqrtf(s_a1)*g_nbl[bb*PP+p], EPSF);
            mrow[2*PP + p] = s_am / fmaxf(sqrtf(s_a3)*sqrtf(s_m3), EPSF);
            mrow[3*PP + p] = amax*s_w4 / fmaxf(sqrtf(s_a4)*fabsf(amax)*g_wn[p], EPSF);
        }
    }
}

// ---------------- metrics b ----------------
__global__ void k_metrics_b(const float* A, const float* Bm, float* out_mb) {
    int bl = blockIdx.x; int bb = bl / LL;
    __shared__ float sb[DD], sm[DD], sl[DD];
    int tid = threadIdx.x;
    sb[tid] = Bm[bl*DD + tid];
    sm[tid] = g_s1m[bl*DD + tid];
    sl[tid] = A[(bb*LL + LL-1)*DD + tid];
    __syncthreads();
    float amax = g_amax1[bl];
    int w = tid >> 5, lane = tid & 31;
    for (int p = w; p < PP; p += 8) {
        float s_ab=0.f, s_b1=0.f, s_am=0.f, s_b3=0.f, s_m3=0.f, s_w4=0.f, s_b4=0.f;
        for (int d = lane; d < DD; d += 32) {
            float bv = sb[d], mv = sm[d], lv = sl[d];
            float w1v = g_ws1[p*DD+d], w3v = g_ws3[p*DD+d], w4v = g_ws4[p*DD+d];
            s_ab += bv*w1v*lv;  s_b1 += bv*bv*w1v;
            s_am += bv*w3v*mv;  s_b3 += bv*bv*w3v;  s_m3 += mv*mv*w3v;
            s_w4 += bv*w4v;     s_b4 += bv*bv*w4v;
        }
        for (int o = 16; o; o >>= 1) {
            s_ab += __shfl_down_sync(0xffffffffu, s_ab, o);
            s_b1 += __shfl_down_sync(0xffffffffu, s_b1, o);
            s_am += __shfl_down_sync(0xffffffffu, s_am, o);
            s_b3 += __shfl_down_sync(0xffffffffu, s_b3, o);
            s_m3 += __shfl_down_sync(0xffffffffu, s_m3, o);
            s_w4 += __shfl_down_sync(0xffffffffu, s_w4, o);
            s_b4 += __shfl_down_sync(0xffffffffu, s_b4, o);
        }
        if (lane == 0) {
            float* mrow = out_mb + bl*MF4;
            mrow[p]        = s_ab / fmaxf(sqrtf(s_b1)*g_nal[bb*PP+p], EPSF);
            mrow[2*PP + p] = s_am / fmaxf(sqrtf(s_b3)*sqrtf(s_m3), EPSF);
            mrow[3*PP + p] = amax*s_w4 / fmaxf(sqrtf(s_b4)*fabsf(amax)*g_wn[p], EPSF);
        }
    }
}

// ---------------- launch (k_cos_mma at index 3 for the ncu window) ----------------
extern "C" void kernel_launch(void* const* d_in, const int* in_sizes, int n_in,
                              void* d_out, int out_size) {
    const float* a  = (const float*)d_in[0];
    const float* b  = (const float*)d_in[1];
    const int* ma   = (const int*)d_in[2];
    const int* mb   = (const int*)d_in[3];
    const float* w1 = (const float*)d_in[4];
    const float* w2 = (const float*)d_in[5];
    const float* w3 = (const float*)d_in[6];
    const float* w4 = (const float*)d_in[7];
    const float* temp = (const float*)d_in[8];

    float* out = (float*)d_out;
    float* out_ia = out;
    float* out_ib = out + NB*LL*DD;
    float* out_ma = out + 2*NB*LL*DD;
    float* out_mb = out_ma + NB*LL*MF4;

    k_prep<<<PP, 256>>>(w1, w2, w3, w4, out_mb);                      // 0
    k_split<<<dim3(NBLL, PP+1), 256>>>(a, b);                         // 1
    k_pnorm<<<dim3(NBLL, 2), 256>>>(a, b);                            // 2
    k_cos_mma<<<dim3(LL/128, PP, NB), 256>>>(out_ma, out_mb);         // 3 <- ncu window
    k_rownorm<<<NBLL, 256>>>(a, b);                                   // 4
    k_gemm_raw<<<dim3(LL/64, LL/128, NB), 256>>>(a, b);               // 5
    k_last<<<NB, 256>>>(a, b);                                        // 6
    k_rowstats<<<NBLL, 256>>>(ma, mb, temp);                          // 7
    k_colstats<<<dim3(LL/32, NB), dim3(32,8)>>>(ma, mb, temp);        // 8
    k_ab<<<dim3(LL/64, DD/64, NB), 256>>>(b, ma, mb, temp, out_ia);   // 9
    k_ba<<<dim3(LL/64, DD/64, NB), 256>>>(a, ma, mb, temp, out_ib);   // 10
    k_metrics_a<<<NBLL, 256>>>(a, b, out_ma);                         // 11
    k_metrics_b<<<NBLL, 256>>>(a, b, out_mb);                         // 12
}

// round 17
// speedup vs baseline: 1.3594x; 1.1344x over previous
#include <cuda_runtime.h>
#include <cuda_fp16.h>
#include <float.h>
#include <math.h>

#define LL 512
#define DD 256
#define PP 20
#define NB 16
#define NBLL (NB*LL)
#define EPSF 1e-8f
#define NEGF -10000000.0f
#define MF4 (4*PP)

typedef unsigned long long u64;

__device__ __forceinline__ void ffma2(u64 &d, u64 a, u64 b) {
    asm("fma.rn.f32x2 %0, %1, %2, %0;" : "+l"(d) : "l"(a), "l"(b));
}
// warp-level fp16 tensor-core MMA (sm_80+, plain target)
__device__ __forceinline__ void mmaf16(float* c, const unsigned* a, const unsigned* b) {
    asm volatile("mma.sync.aligned.m16n8k16.row.col.f32.f16.f16.f32 "
        "{%0,%1,%2,%3}, {%4,%5,%6,%7}, {%8,%9}, {%0,%1,%2,%3};"
        : "+f"(c[0]), "+f"(c[1]), "+f"(c[2]), "+f"(c[3])
        : "r"(a[0]), "r"(a[1]), "r"(a[2]), "r"(a[3]), "r"(b[0]), "r"(b[1]));
}

// ---------------- device scratch (allocation-free) ----------------
static __device__ float g_raw[NB*LL*LL];
static __device__ unsigned g_apk[(size_t)PP*NBLL*128];  // (a*ws2_p) hi fp16 pairs
static __device__ u64 g_bmix[(size_t)NBLL*128];         // b: (hi-pair u32, lo-pair u32) fp16
static __device__ float g_s2m[NB*LL*DD];
static __device__ float g_s1m[NB*LL*DD];
static __device__ float g_nra[NBLL];
static __device__ float g_nrb[NBLL];
static __device__ float g_rowmax[NBLL];
static __device__ float g_rowsuminv[NBLL];
static __device__ float g_arowsuminv[NBLL];
static __device__ float g_amax2[NBLL];
static __device__ float g_colmax[NBLL];
static __device__ float g_colsuminv[NBLL];
static __device__ float g_acolsuminv[NBLL];
static __device__ float g_amax1[NBLL];
static __device__ float g_na2[PP*NBLL];   // [p][bl]
static __device__ float g_nb2[PP*NBLL];   // [p][bl]
static __device__ float g_ws1[PP*DD];
static __device__ float g_ws2[PP*DD];
static __device__ float g_ws3[PP*DD];
static __device__ float g_ws4[PP*DD];
static __device__ float g_nbl[NB*PP];
static __device__ float g_nal[NB*PP];
static __device__ float g_wn[PP];

__device__ __forceinline__ void atomicMaxF(float* addr, float v) {
    int old = __float_as_int(*addr);
    while (__int_as_float(old) < v) {
        int prev = atomicCAS((int*)addr, old, __float_as_int(v));
        if (prev == old) break;
        old = prev;
    }
}

// ---------------- prep: squared weights + wn + mm_b init ----------------
__global__ void k_prep(const float* w1, const float* w2, const float* w3, const float* w4,
                       float* out_mb) {
    int p = blockIdx.x, d = threadIdx.x;
    float v1 = w1[p*DD+d]; g_ws1[p*DD+d] = v1*v1;
    float v2 = w2[p*DD+d]; g_ws2[p*DD+d] = v2*v2;
    float v3 = w3[p*DD+d]; g_ws3[p*DD+d] = v3*v3;
    float v4 = w4[p*DD+d]; float s4 = v4*v4; g_ws4[p*DD+d] = s4;
    __shared__ float red[256];
    red[d] = s4; __syncthreads();
    for (int o = 128; o; o >>= 1) { if (d < o) red[d] += red[d+o]; __syncthreads(); }
    if (d == 0) g_wn[p] = sqrtf(red[0]);
    for (int idx = blockIdx.x*256 + d; idx < NB*LL*PP; idx += PP*256) {
        int bl = idx / PP, pp = idx % PP;
        out_mb[bl*MF4 + PP + pp] = -FLT_MAX;
    }
}

// ---------------- splits: p<PP -> a*ws2_p hi (fp16) ; p==PP -> b hi/lo (fp16) ----------------
__global__ void k_split(const float* A, const float* Bm) {
    int bl = blockIdx.x; int p = blockIdx.y; int d = threadIdx.x;
    float v;
    if (p < PP) v = A[bl*DD + d] * g_ws2[p*DD + d];
    else        v = Bm[bl*DD + d];
    __half h = __float2half(v);
    __half l = __float2half(v - __half2float(h));
    unsigned hs = (unsigned)__half_as_ushort(h);
    unsigned ls = (unsigned)__half_as_ushort(l);
    unsigned hn = __shfl_down_sync(0xffffffffu, hs, 1);
    unsigned ln = __shfl_down_sync(0xffffffffu, ls, 1);
    if ((d & 1) == 0) {
        unsigned hp = hs | (hn << 16);   // low half = element k (little-endian)
        unsigned lp = ls | (ln << 16);
        if (p < PP) g_apk[((size_t)p*NBLL + bl)*128 + (d >> 1)] = hp;
        else        g_bmix[(size_t)bl*128 + (d >> 1)] = (u64)hp | ((u64)lp << 32);
    }
}

// ---------------- plain L2 row norms ----------------
__global__ void k_rownorm(const float* A, const float* Bm) {
    int bl = blockIdx.x; int d = threadIdx.x;
    __shared__ float ra[256], rb[256];
    float av = A[bl*DD+d], bv = Bm[bl*DD+d];
    ra[d] = av*av; rb[d] = bv*bv; __syncthreads();
    for (int o = 128; o; o >>= 1) {
        if (d < o) { ra[d] += ra[d+o]; rb[d] += rb[d+o]; }
        __syncthreads();
    }
    if (d == 0) { g_nra[bl] = sqrtf(ra[0]); g_nrb[bl] = sqrtf(rb[0]); }
}

// ---------------- last-row weighted norms (w1^2) ----------------
__global__ void k_last(const float* A, const float* Bm) {
    int bb = blockIdx.x; int tid = threadIdx.x;
    int w = tid >> 5, lane = tid & 31;
    const float* al = A  + (bb*LL + LL-1)*DD;
    const float* bl_ = Bm + (bb*LL + LL-1)*DD;
    for (int p = w; p < PP; p += 8) {
        float sa = 0.f, sb = 0.f;
        for (int d = lane; d < DD; d += 32) {
            float wv = g_ws1[p*DD+d];
            float av = al[d], bv = bl_[d];
            sa += av*av*wv; sb += bv*bv*wv;
        }
        for (int o = 16; o; o >>= 1) {
            sa += __shfl_down_sync(0xffffffffu, sa, o);
            sb += __shfl_down_sync(0xffffffffu, sb, o);
        }
        if (lane == 0) { g_nal[bb*PP+p] = sqrtf(sa); g_nbl[bb*PP+p] = sqrtf(sb); }
    }
}

// ---------------- weighted norms for cos (w2^2), [p][bl] ----------------
__global__ void k_pnorm(const float* A, const float* Bm) {
    int bl = blockIdx.x; int side = blockIdx.y;
    const float* X = side ? Bm : A;
    float* out = side ? g_nb2 : g_na2;
    __shared__ float sx[DD];
    int tid = threadIdx.x;
    float v = X[bl*DD+tid]; sx[tid] = v*v;
    __syncthreads();
    int w = tid >> 5, lane = tid & 31;
    for (int p = w; p < PP; p += 8) {
        float s = 0.f;
        for (int d = lane; d < DD; d += 32) s += sx[d]*g_ws2[p*DD+d];
        for (int o = 16; o; o >>= 1) s += __shfl_down_sync(0xffffffffu, s, o);
        if (lane == 0) out[p*NBLL + bl] = sqrtf(s);
    }
}

// ---------------- cos tensor: fp16 2-term mma, 32x32 warp tiles, pipelined ----------------
__global__ __launch_bounds__(256) void k_cos_mma(float* out_ma, float* out_mb) {
    int bb = blockIdx.z, p = blockIdx.y, i0 = blockIdx.x*128;
    int tid = threadIdx.x, w = tid >> 5, lane = tid & 31;
    int g = lane >> 2, tg = lane & 3;
    int wi = w >> 1, wj = w & 1;
    int iBase = wi*32, jBase = wj*32;
    __shared__ unsigned Ap[2][128*9];
    __shared__ u64 Bm2[2][64*9];
    __shared__ float nb_s[512];
    __shared__ float redc[8][32];
    nb_s[tid]       = g_nb2[p*NBLL + bb*LL + tid];
    nb_s[tid + 256] = g_nb2[p*NBLL + bb*LL + tid + 256];
    float na00 = g_na2[p*NBLL + bb*LL + i0 + iBase + g];
    float na01 = g_na2[p*NBLL + bb*LL + i0 + iBase + g + 8];
    float na10 = g_na2[p*NBLL + bb*LL + i0 + iBase + 16 + g];
    float na11 = g_na2[p*NBLL + bb*LL + i0 + iBase + 16 + g + 8];
    const unsigned* gap = g_apk + ((size_t)p*NBLL + bb*LL + i0)*128;
    const u64* gbm = g_bmix + (size_t)(bb*LL)*128;
    float rmax[2][2] = {{-FLT_MAX, -FLT_MAX}, {-FLT_MAX, -FLT_MAX}};
    const int r_a = tid >> 3, c_a = tid & 7;
    float acc[2][4][4] = {};

    // prologue: stage t=0 into buf 0
    #pragma unroll
    for (int e = 0; e < 4; e++)
        Ap[0][(r_a + e*32)*9 + c_a] = gap[(size_t)(r_a + e*32)*128 + c_a];
    #pragma unroll
    for (int e = 0; e < 2; e++)
        Bm2[0][(r_a + e*32)*9 + c_a] = gbm[(size_t)(r_a + e*32)*128 + c_a];
    __syncthreads();

    #pragma unroll 1
    for (int t = 0; t < 128; t++) {
        int buf = t & 1;
        // prefetch t+1 into registers
        unsigned ra[4]; u64 rb[2];
        if (t + 1 < 128) {
            int kp0n = ((t + 1) & 15) * 8;
            int j0n = ((t + 1) >> 4) * 64;
            #pragma unroll
            for (int e = 0; e < 4; e++)
                ra[e] = gap[(size_t)(r_a + e*32)*128 + kp0n + c_a];
            #pragma unroll
            for (int e = 0; e < 2; e++)
                rb[e] = gbm[(size_t)(j0n + r_a + e*32)*128 + kp0n + c_a];
        }
        // A hi fragments (two 16-row i-tiles)
        unsigned ah0[4], ah1[4];
        ah0[0] = Ap[buf][(iBase + g     )*9 + tg];
        ah0[1] = Ap[buf][(iBase + g + 8 )*9 + tg];
        ah0[2] = Ap[buf][(iBase + g     )*9 + tg + 4];
        ah0[3] = Ap[buf][(iBase + g + 8 )*9 + tg + 4];
        ah1[0] = Ap[buf][(iBase + 16 + g    )*9 + tg];
        ah1[1] = Ap[buf][(iBase + 16 + g + 8)*9 + tg];
        ah1[2] = Ap[buf][(iBase + 16 + g    )*9 + tg + 4];
        ah1[3] = Ap[buf][(iBase + 16 + g + 8)*9 + tg + 4];
        #pragma unroll
        for (int nt = 0; nt < 4; nt++) {
            u64 b0 = Bm2[buf][(jBase + nt*8 + g)*9 + tg];
            u64 b1 = Bm2[buf][(jBase + nt*8 + g)*9 + tg + 4];
            unsigned bh[2], bl[2];
            bh[0] = (unsigned)b0; bl[0] = (unsigned)(b0 >> 32);
            bh[1] = (unsigned)b1; bl[1] = (unsigned)(b1 >> 32);
            mmaf16(acc[0][nt], ah0, bh);
            mmaf16(acc[0][nt], ah0, bl);
            mmaf16(acc[1][nt], ah1, bh);
            mmaf16(acc[1][nt], ah1, bl);
        }
        // store t+1 into other buffer
        if (t + 1 < 128) {
            #pragma unroll
            for (int e = 0; e < 4; e++)
                Ap[buf^1][(r_a + e*32)*9 + c_a] = ra[e];
            #pragma unroll
            for (int e = 0; e < 2; e++)
                Bm2[buf^1][(r_a + e*32)*9 + c_a] = rb[e];
        }
        // epilogue per j-tile
        if ((t & 15) == 15) {
            int j0 = (t >> 4) * 64;
            #pragma unroll
            for (int nt = 0; nt < 4; nt++) {
                int c0 = j0 + jBase + nt*8 + tg*2, c1 = c0 + 1;
                float d0 = nb_s[c0 - j0 + j0], d1v = nb_s[c1 - j0 + j0]; // nb_s indexed by full col
                float v00 = acc[0][nt][0] / (na00*nb_s[c0] + EPSF);
                float v01 = acc[0][nt][1] / (na00*nb_s[c1] + EPSF);
                float v10 = acc[0][nt][2] / (na01*nb_s[c0] + EPSF);
                float v11 = acc[0][nt][3] / (na01*nb_s[c1] + EPSF);
                float u00 = acc[1][nt][0] / (na10*nb_s[c0] + EPSF);
                float u01 = acc[1][nt][1] / (na10*nb_s[c1] + EPSF);
                float u10 = acc[1][nt][2] / (na11*nb_s[c0] + EPSF);
                float u11 = acc[1][nt][3] / (na11*nb_s[c1] + EPSF);
                (void)d0; (void)d1v;
                rmax[0][0] = fmaxf(rmax[0][0], fmaxf(v00, v01));
                rmax[0][1] = fmaxf(rmax[0][1], fmaxf(v10, v11));
                rmax[1][0] = fmaxf(rmax[1][0], fmaxf(u00, u01));
                rmax[1][1] = fmaxf(rmax[1][1], fmaxf(u10, u11));
                float cm0 = fmaxf(fmaxf(v00, v10), fmaxf(u00, u10));
                float cm1 = fmaxf(fmaxf(v01, v11), fmaxf(u01, u11));
                cm0 = fmaxf(cm0, __shfl_xor_sync(0xffffffffu, cm0, 4));
                cm1 = fmaxf(cm1, __shfl_xor_sync(0xffffffffu, cm1, 4));
                cm0 = fmaxf(cm0, __shfl_xor_sync(0xffffffffu, cm0, 8));
                cm1 = fmaxf(cm1, __shfl_xor_sync(0xffffffffu, cm1, 8));
                cm0 = fmaxf(cm0, __shfl_xor_sync(0xffffffffu, cm0, 16));
                cm1 = fmaxf(cm1, __shfl_xor_sync(0xffffffffu, cm1, 16));
                if (g == 0) {
                    redc[w][nt*8 + tg*2]     = cm0;
                    redc[w][nt*8 + tg*2 + 1] = cm1;
                }
                #pragma unroll
                for (int q = 0; q < 4; q++) { acc[0][nt][q] = 0.f; acc[1][nt][q] = 0.f; }
            }
            __syncthreads();
            if (tid < 64) {
                int wjv = tid >> 5, loc = tid & 31;
                float m = redc[wjv][loc];
                m = fmaxf(m, redc[2 + wjv][loc]);
                m = fmaxf(m, redc[4 + wjv][loc]);
                m = fmaxf(m, redc[6 + wjv][loc]);
                atomicMaxF(&out_mb[(bb*LL + j0 + tid)*MF4 + PP + p], m);
            }
        }
        __syncthreads();
    }
    // row-max: reduce over tg, then combine the two wj-warps via smem
    #pragma unroll
    for (int o = 1; o <= 2; o <<= 1) {
        rmax[0][0] = fmaxf(rmax[0][0], __shfl_xor_sync(0xffffffffu, rmax[0][0], o));
        rmax[0][1] = fmaxf(rmax[0][1], __shfl_xor_sync(0xffffffffu, rmax[0][1], o));
        rmax[1][0] = fmaxf(rmax[1][0], __shfl_xor_sync(0xffffffffu, rmax[1][0], o));
        rmax[1][1] = fmaxf(rmax[1][1], __shfl_xor_sync(0xffffffffu, rmax[1][1], o));
    }
    if (tg == 0) {
        redc[w][g]        = rmax[0][0];
        redc[w][g + 8]    = rmax[0][1];
        redc[w][16 + g]   = rmax[1][0];
        redc[w][24 + g]   = rmax[1][1];
    }
    __syncthreads();
    if (tid < 128) {
        int wiv = tid >> 5, loc = tid & 31;
        float m = fmaxf(redc[wiv*2][loc], redc[wiv*2 + 1][loc]);
        out_ma[(bb*LL + i0 + wiv*32 + loc)*MF4 + PP + p] = m;
    }
}

// ---------------- raw = a @ b^T : FFMA2 A-dup + register-prefetch (R10-proven) ----------------
__global__ __launch_bounds__(256, 2) void k_gemm_raw(const float* A, const float* Bm) {
    int bb = blockIdx.z; int i0 = blockIdx.y*128; int j0 = blockIdx.x*64;
    int tid = threadIdx.x;
    int tx = tid & 15, ty = tid >> 4;
    __shared__ float Ad[2][16][260];
    __shared__ float Bs[16][68];
    const int c_ld = tid & 15;
    const int r_ld = tid >> 4;
    u64 acc[8][2] = {};
    float pa[8], pb[4];
    #pragma unroll
    for (int e = 0; e < 8; e++)
        pa[e] = A[(bb*LL + i0 + r_ld + e*16)*DD + c_ld];
    #pragma unroll
    for (int e = 0; e < 4; e++)
        pb[e] = Bm[(bb*LL + j0 + r_ld + e*16)*DD + c_ld];
    #pragma unroll
    for (int e = 0; e < 8; e++)
        *(float2*)&Ad[0][c_ld][2*(r_ld + e*16)] = make_float2(pa[e], pa[e]);
    #pragma unroll
    for (int e = 0; e < 4; e++)
        Bs[c_ld][r_ld + e*16] = pb[e];

    #pragma unroll 1
    for (int s = 0; s < 16; s++) {
        int buf = s & 1;
        __syncthreads();
        if (s + 1 < 16) {
            int k0n = (s + 1) * 16;
            #pragma unroll
            for (int e = 0; e < 8; e++)
                pa[e] = A[(bb*LL + i0 + r_ld + e*16)*DD + k0n + c_ld];
            #pragma unroll
            for (int e = 0; e < 4; e++)
                pb[e] = Bm[(bb*LL + j0 + r_ld + e*16)*DD + k0n + c_ld];
        }
        #pragma unroll
        for (int kk = 0; kk < 16; kk++) {
            u64 Ar[8], Br[2];
            ulonglong2 t;
            t = *(const ulonglong2*)&Ad[buf][kk][ty*16   ]; Ar[0]=t.x; Ar[1]=t.y;
            t = *(const ulonglong2*)&Ad[buf][kk][ty*16+ 4]; Ar[2]=t.x; Ar[3]=t.y;
            t = *(const ulonglong2*)&Ad[buf][kk][ty*16+ 8]; Ar[4]=t.x; Ar[5]=t.y;
            t = *(const ulonglong2*)&Ad[buf][kk][ty*16+12]; Ar[6]=t.x; Ar[7]=t.y;
            t = *(const ulonglong2*)&Bs[kk][tx*4]; Br[0]=t.x; Br[1]=t.y;
            #pragma unroll
            for (int r = 0; r < 8; r++) {
                ffma2(acc[r][0], Ar[r], Br[0]);
                ffma2(acc[r][1], Ar[r], Br[1]);
            }
        }
        __syncthreads();
        if (s + 1 < 16) {
            #pragma unroll
            for (int e = 0; e < 8; e++)
                *(float2*)&Ad[buf^1][c_ld][2*(r_ld + e*16)] = make_float2(pa[e], pa[e]);
            #pragma unroll
            for (int e = 0; e < 4; e++)
                Bs[c_ld][r_ld + e*16] = pb[e];
        }
    }
    #pragma unroll
    for (int r = 0; r < 8; r++) {
        ulonglong2 v; v.x = acc[r][0]; v.y = acc[r][1];
        *(ulonglong2*)&g_raw[(bb*LL + i0 + ty*8 + r)*LL + j0 + tx*4] = v;
    }
}

// ---------------- per-row stats ----------------
__global__ void k_rowstats(const int* ma, const int* mb, const float* temp_p) {
    int bl = blockIdx.x; int bb = bl / LL;
    int tid = threadIdx.x;
    __shared__ float s[LL];
    s[tid]       = g_raw[bl*LL + tid];
    s[tid + 256] = g_raw[bl*LL + tid + 256];
    __syncthreads();
    float temp = temp_p[0];
    int mai = ma[bl];
    float nrai = g_nra[bl];
    float mx = -FLT_MAX, amx = -FLT_MAX, asum = 0.f;
    for (int j = tid; j < LL; j += 256) {
        float rv = s[j];
        float attn = (mai && mb[bb*LL+j]) ? rv*temp : NEGF;
        mx = fmaxf(mx, attn);
        float al = rv / (nrai*g_nrb[bb*LL+j] + EPSF);
        amx = fmaxf(amx, al); asum += al;
    }
    __shared__ float red[256];
    red[tid] = mx; __syncthreads();
    for (int o = 128; o; o >>= 1) { if (tid < o) red[tid] = fmaxf(red[tid], red[tid+o]); __syncthreads(); }
    float MX = red[0]; __syncthreads();
    red[tid] = amx; __syncthreads();
    for (int o = 128; o; o >>= 1) { if (tid < o) red[tid] = fmaxf(red[tid], red[tid+o]); __syncthreads(); }
    float AMX = red[0]; __syncthreads();
    red[tid] = asum; __syncthreads();
    for (int o = 128; o; o >>= 1) { if (tid < o) red[tid] += red[tid+o]; __syncthreads(); }
    float ASUM = red[0]; __syncthreads();
    float se = 0.f;
    for (int j = tid; j < LL; j += 256) {
        float rv = s[j];
        float attn = (mai && mb[bb*LL+j]) ? rv*temp : NEGF;
        se += expf(attn - MX);
    }
    red[tid] = se; __syncthreads();
    for (int o = 128; o; o >>= 1) { if (tid < o) red[tid] += red[tid+o]; __syncthreads(); }
    if (tid == 0) {
        g_rowmax[bl] = MX;
        g_rowsuminv[bl] = 1.0f/red[0];
        g_arowsuminv[bl] = 1.0f/ASUM;
        g_amax2[bl] = AMX;
    }
}

// ---------------- per-col stats ----------------
__global__ void k_colstats(const int* ma, const int* mb, const float* temp_p) {
    int bb = blockIdx.y; int j = blockIdx.x*32 + threadIdx.x;
    int tx = threadIdx.x, ty = threadIdx.y;
    float temp = temp_p[0];
    int mbj = mb[bb*LL+j];
    float nrbj = g_nrb[bb*LL+j];
    float mx = -FLT_MAX, amx = -FLT_MAX, asum = 0.f;
    for (int i = ty; i < LL; i += 8) {
        float rv = g_raw[(bb*LL+i)*LL + j];
        float attn = (ma[bb*LL+i] && mbj) ? rv*temp : NEGF;
        mx = fmaxf(mx, attn);
        float al = rv / (g_nra[bb*LL+i]*nrbj + EPSF);
        amx = fmaxf(amx, al); asum += al;
    }
    __shared__ float r1[8][32], r2[8][32], r3[8][32];
    __shared__ float cm[32], cam[32], cas[32];
    r1[ty][tx] = mx; r2[ty][tx] = amx; r3[ty][tx] = asum;
    __syncthreads();
    if (ty == 0) {
        float m = r1[0][tx], a2 = r2[0][tx], s = r3[0][tx];
        for (int k = 1; k < 8; k++) { m = fmaxf(m, r1[k][tx]); a2 = fmaxf(a2, r2[k][tx]); s += r3[k][tx]; }
        cm[tx] = m; cam[tx] = a2; cas[tx] = s;
    }
    __syncthreads();
    float MX = cm[tx];
    float se = 0.f;
    for (int i = ty; i < LL; i += 8) {
        float rv = g_raw[(bb*LL+i)*LL + j];
        float attn = (ma[bb*LL+i] && mbj) ? rv*temp : NEGF;
        se += expf(attn - MX);
    }
    __syncthreads();
    r1[ty][tx] = se; __syncthreads();
    if (ty == 0) {
        float s = r1[0][tx];
        for (int k = 1; k < 8; k++) s += r1[k][tx];
        int idx = bb*LL+j;
        g_colmax[idx] = MX;
        g_colsuminv[idx] = 1.0f/s;
        g_acolsuminv[idx] = 1.0f/cas[tx];
        g_amax1[idx] = cam[tx];
    }
}

// ---------------- ia / s2_mean : FFMA2 dup-P/Q (proven) ----------------
__global__ __launch_bounds__(256) void k_ab(const float* Bm, const int* ma, const int* mb,
                                            const float* temp_p, float* out_ia) {
    int bb = blockIdx.z; int i0 = blockIdx.x*64; int d0 = blockIdx.y*64;
    int tid = threadIdx.x;
    int tx = tid & 15, ty = tid >> 4;
    float temp = temp_p[0];
    __shared__ float Pd[16][132], Qd[16][132], Bs[16][68];
    u64 accP[4][2] = {}, accQ[4][2] = {};
    for (int k0 = 0; k0 < LL; k0 += 16) {
        #pragma unroll
        for (int e = 0; e < 4; e++) {
            int idx = tid + e*256;
            int r = idx >> 4, c = idx & 15;
            int gi = bb*LL + i0 + r, gj = bb*LL + k0 + c;
            float rv = g_raw[gi*LL + k0 + c];
            float attn = (ma[gi] && mb[gj]) ? rv*temp : NEGF;
            float pv = expf(attn - g_rowmax[gi]) * g_rowsuminv[gi];
            float qv = rv / (g_nra[gi]*g_nrb[gj] + EPSF) * g_arowsuminv[gi];
            *(float2*)&Pd[c][2*r] = make_float2(pv, pv);
            *(float2*)&Qd[c][2*r] = make_float2(qv, qv);
        }
        #pragma unroll
        for (int e = 0; e < 4; e++) {
            int idx = tid + e*256; int r = idx >> 6, c = idx & 63;
            Bs[r][c] = Bm[(bb*LL + k0 + r)*DD + d0 + c];
        }
        __syncthreads();
        #pragma unroll
        for (int kk = 0; kk < 16; kk++) {
            u64 Pr[4], Qr[4], Br[2];
            ulonglong2 t;
            t = *(const ulonglong2*)&Pd[kk][ty*8   ]; Pr[0]=t.x; Pr[1]=t.y;
            t = *(const ulonglong2*)&Pd[kk][ty*8+ 4]; Pr[2]=t.x; Pr[3]=t.y;
            t = *(const ulonglong2*)&Qd[kk][ty*8   ]; Qr[0]=t.x; Qr[1]=t.y;
            t = *(const ulonglong2*)&Qd[kk][ty*8+ 4]; Qr[2]=t.x; Qr[3]=t.y;
            t = *(const ulonglong2*)&Bs[kk][tx*4]; Br[0]=t.x; Br[1]=t.y;
            #pragma unroll
            for (int r = 0; r < 4; r++) {
                ffma2(accP[r][0], Pr[r], Br[0]);
                ffma2(accP[r][1], Pr[r], Br[1]);
                ffma2(accQ[r][0], Qr[r], Br[0]);
                ffma2(accQ[r][1], Qr[r], Br[1]);
            }
        }
        __syncthreads();
    }
    #pragma unroll
    for (int r = 0; r < 4; r++) {
        int gi = bb*LL + i0 + ty*4 + r;
        ulonglong2 vp; vp.x = accP[r][0]; vp.y = accP[r][1];
        ulonglong2 vq; vq.x = accQ[r][0]; vq.y = accQ[r][1];
        *(ulonglong2*)&out_ia[gi*DD + d0 + tx*4] = vp;
        *(ulonglong2*)&g_s2m [gi*DD + d0 + tx*4] = vq;
    }
}

// ---------------- ib / s1_mean : FFMA2 dup-P/Q (proven) ----------------
__global__ __launch_bounds__(256) void k_ba(const float* A, const int* ma, const int* mb,
                                            const float* temp_p, float* out_ib) {
    int bb = blockIdx.z; int j0 = blockIdx.x*64; int d0 = blockIdx.y*64;
    int tid = threadIdx.x;
    int tx = tid & 15, ty = tid >> 4;
    float temp = temp_p[0];
    __shared__ float Pd[16][132], Qd[16][132], As[16][68];
    u64 accP[4][2] = {}, accQ[4][2] = {};
    for (int k0 = 0; k0 < LL; k0 += 16) {
        #pragma unroll
        for (int e = 0; e < 4; e++) {
            int idx = tid + e*256;
            int r = idx >> 6, c = idx & 63;
            int gi = bb*LL + k0 + r, gj = bb*LL + j0 + c;
            float rv = g_raw[gi*LL + j0 + c];
            float attn = (ma[gi] && mb[gj]) ? rv*temp : NEGF;
            float pv = expf(attn - g_colmax[gj]) * g_colsuminv[gj];
            float qv = rv / (g_nra[gi]*g_nrb[gj] + EPSF) * g_acolsuminv[gj];
            *(float2*)&Pd[r][2*c] = make_float2(pv, pv);
            *(float2*)&Qd[r][2*c] = make_float2(qv, qv);
            As[r][c] = A[(bb*LL + k0 + r)*DD + d0 + c];
        }
        __syncthreads();
        #pragma unroll
        for (int kk = 0; kk < 16; kk++) {
            u64 Pr[4], Qr[4], Br[2];
            ulonglong2 t;
            t = *(const ulonglong2*)&Pd[kk][ty*8   ]; Pr[0]=t.x; Pr[1]=t.y;
            t = *(const ulonglong2*)&Pd[kk][ty*8+ 4]; Pr[2]=t.x; Pr[3]=t.y;
            t = *(const ulonglong2*)&Qd[kk][ty*8   ]; Qr[0]=t.x; Qr[1]=t.y;
            t = *(const ulonglong2*)&Qd[kk][ty*8+ 4]; Qr[2]=t.x; Qr[3]=t.y;
            t = *(const ulonglong2*)&As[kk][tx*4]; Br[0]=t.x; Br[1]=t.y;
            #pragma unroll
            for (int r = 0; r < 4; r++) {
                ffma2(accP[r][0], Pr[r], Br[0]);
                ffma2(accP[r][1], Pr[r], Br[1]);
                ffma2(accQ[r][0], Qr[r], Br[0]);
                ffma2(accQ[r][1], Qr[r], Br[1]);
            }
        }
        __syncthreads();
    }
    #pragma unroll
    for (int r = 0; r < 4; r++) {
        int gj = bb*LL + j0 + ty*4 + r;
        ulonglong2 vp; vp.x = accP[r][0]; vp.y = accP[r][1];
        ulonglong2 vq; vq.x = accQ[r][0]; vq.y = accQ[r][1];
        *(ulonglong2*)&out_ib[gj*DD + d0 + tx*4] = vp;
        *(ulonglong2*)&g_s1m [gj*DD + d0 + tx*4] = vq;
    }
}

// ---------------- metrics a ----------------
__global__ void k_metrics_a(const float* A, const float* Bm, float* out_ma) {
    int bl = blockIdx.x; int bb = bl / LL;
    __shared__ float sa[DD], sm[DD], sl[DD];
    int tid = threadIdx.x;
    sa[tid] = A[bl*DD + tid];
    sm[tid] = g_s2m[bl*DD + tid];
    sl[tid] = Bm[(bb*LL + LL-1)*DD + tid];
    __syncthreads();
    float amax = g_amax2[bl];
    int w = tid >> 5, lane = tid & 31;
    for (int p = w; p < PP; p += 8) {
        float s_ab=0.f, s_a1=0.f, s_am=0.f, s_a3=0.f, s_m3=0.f, s_w4=0.f, s_a4=0.f;
        for (int d = lane; d < DD; d += 32) {
            float av = sa[d], mv = sm[d], lv = sl[d];
            float w1v = g_ws1[p*DD+d], w3v = g_ws3[p*DD+d], w4v = g_ws4[p*DD+d];
            s_ab += av*w1v*lv;  s_a1 += av*av*w1v;
            s_am += av*w3v*mv;  s_a3 += av*av*w3v;  s_m3 += mv*mv*w3v;
            s_w4 += av*w4v;     s_a4 += av*av*w4v;
        }
        for (int o = 16; o; o >>= 1) {
            s_ab += __shfl_down_sync(0xffffffffu, s_ab, o);
            s_a1 += __shfl_down_sync(0xffffffffu, s_a1, o);
            s_am += __shfl_down_sync(0xffffffffu, s_am, o);
            s_a3 += __shfl_down_sync(0xffffffffu, s_a3, o);
            s_m3 += __shfl_down_sync(0xffffffffu, s_m3, o);
            s_w4 += __shfl_down_sync(0xffffffffu, s_w4, o);
            s_a4 += __shfl_down_sync(0xffffffffu, s_a4, o);
        }
        if (lane == 0) {
            float* mrow = out_ma + bl*MF4;
            mrow[p]        = s_ab / fmaxf(sqrtf(s_a1)*g_nbl[bb*PP+p], EPSF);
            mrow[2*PP + p] = s_am / fmaxf(sqrtf(s_a3)*sqrtf(s_m3), EPSF);
            mrow[3*PP + p] = amax*s_w4 / fmaxf(sqrtf(s_a4)*fabsf(amax)*g_wn[p], EPSF);
        }
    }
}

// ---------------- metrics b ----------------
__global__ void k_metrics_b(const float* A, const float* Bm, float* out_mb) {
    int bl = blockIdx.x; int bb = bl / LL;
    __shared__ float sb[DD], sm[DD], sl[DD];
    int tid = threadIdx.x;
    sb[tid] = Bm[bl*DD + tid];
    sm[tid] = g_s1m[bl*DD + tid];
    sl[tid] = A[(bb*LL + LL-1)*DD + tid];
    __syncthreads();
    float amax = g_amax1[bl];
    int w = tid >> 5, lane = tid & 31;
    for (int p = w; p < PP; p += 8) {
        float s_ab=0.f, s_b1=0.f, s_am=0.f, s_b3=0.f, s_m3=0.f, s_w4=0.f, s_b4=0.f;
        for (int d = lane; d < DD; d += 32) {
            float bv = sb[d], mv = sm[d], lv = sl[d];
            float w1v = g_ws1[p*DD+d], w3v = g_ws3[p*DD+d], w4v = g_ws4[p*DD+d];
            s_ab += bv*w1v*lv;  s_b1 += bv*bv*w1v;
            s_am += bv*w3v*mv;  s_b3 += bv*bv*w3v;  s_m3 += mv*mv*w3v;
            s_w4 += bv*w4v;     s_b4 += bv*bv*w4v;
        }
        for (int o = 16; o; o >>= 1) {
            s_ab += __shfl_down_sync(0xffffffffu, s_ab, o);
            s_b1 += __shfl_down_sync(0xffffffffu, s_b1, o);
            s_am += __shfl_down_sync(0xffffffffu, s_am, o);
            s_b3 += __shfl_down_sync(0xffffffffu, s_b3, o);
            s_m3 += __shfl_down_sync(0xffffffffu, s_m3, o);
            s_w4 += __shfl_down_sync(0xffffffffu, s_w4, o);
            s_b4 += __shfl_down_sync(0xffffffffu, s_b4, o);
        }
        if (lane == 0) {
            float* mrow = out_mb + bl*MF4;
            mrow[p]        = s_ab / fmaxf(sqrtf(s_b1)*g_nal[bb*PP+p], EPSF);
            mrow[2*PP + p] = s_am / fmaxf(sqrtf(s_b3)*sqrtf(s_m3), EPSF);
            mrow[3*PP + p] = amax*s_w4 / fmaxf(sqrtf(s_b4)*fabsf(amax)*g_wn[p], EPSF);
        }
    }
}

// ---------------- launch (k_cos_mma at index 3 for the ncu window) ----------------
extern "C" void kernel_launch(void* const* d_in, const int* in_sizes, int n_in,
                              void* d_out, int out_size) {
    const float* a  = (const float*)d_in[0];
    const float* b  = (const float*)d_in[1];
    const int* ma   = (const int*)d_in[2];
    const int* mb   = (const int*)d_in[3];
    const float* w1 = (const float*)d_in[4];
    const float* w2 = (const float*)d_in[5];
    const float* w3 = (const float*)d_in[6];
    const float* w4 = (const float*)d_in[7];
    const float* temp = (const float*)d_in[8];

    float* out = (float*)d_out;
    float* out_ia = out;
    float* out_ib = out + NB*LL*DD;
    float* out_ma = out + 2*NB*LL*DD;
    float* out_mb = out_ma + NB*LL*MF4;

    k_prep<<<PP, 256>>>(w1, w2, w3, w4, out_mb);                      // 0
    k_split<<<dim3(NBLL, PP+1), 256>>>(a, b);                         // 1
    k_pnorm<<<dim3(NBLL, 2), 256>>>(a, b);                            // 2
    k_cos_mma<<<dim3(LL/128, PP, NB), 256>>>(out_ma, out_mb);         // 3 <- ncu window
    k_rownorm<<<NBLL, 256>>>(a, b);                                   // 4
    k_gemm_raw<<<dim3(LL/64, LL/128, NB), 256>>>(a, b);               // 5
    k_last<<<NB, 256>>>(a, b);                                        // 6
    k_rowstats<<<NBLL, 256>>>(ma, mb, temp);                          // 7
    k_colstats<<<dim3(LL/32, NB), dim3(32,8)>>>(ma, mb, temp);        // 8
    k_ab<<<dim3(LL/64, DD/64, NB), 256>>>(b, ma, mb, temp, out_ia);   // 9
    k_ba<<<dim3(LL/64, DD/64, NB), 256>>>(a, ma, mb, temp, out_ib);   // 10
    k_metrics_a<<<NBLL, 256>>>(a, b, out_ma);                         // 11
    k_metrics_b<<<NBLL, 256>>>(a, b, out_mb);                         // 12
}